// round 1
// baseline (speedup 1.0000x reference)
#include <cuda_runtime.h>
#include <cstdint>

#define N_HEAD   32
#define HEAD_DIM 32
#define N_EMBD   1024
#define VOCAB    32000
#define NTOK     128        // B*T = 2*64
#define TEMP_MIN 0.1f

typedef unsigned long long u64;

// Collapsed vocab matrix: S[h,v] = sum_d vocab_emb[v, h*32+d], stored column-major
// (column v = 32 contiguous floats) for vectorized 128-bit loads.
__device__ __align__(256) float g_S[VOCAB * N_HEAD];

// ---------- packed f32x2 helpers (ptxas never auto-fuses these) ----------
#define FMA2(d, a, b, c) asm("fma.rn.f32x2 %0, %1, %2, %3;" : "=l"(d) : "l"(a), "l"(b), "l"(c))
#define ADD2(d, a, b)    asm("add.rn.f32x2 %0, %1, %2;"      : "=l"(d) : "l"(a), "l"(b))
#define MUL2(d, a, b)    asm("mul.rn.f32x2 %0, %1, %2;"      : "=l"(d) : "l"(a), "l"(b))

static __device__ __forceinline__ u64 pack2(float lo, float hi) {
    u64 r; asm("mov.b64 %0, {%1, %2};" : "=l"(r) : "f"(lo), "f"(hi)); return r;
}
static __device__ __forceinline__ void unpack2(u64 v, float& lo, float& hi) {
    asm("mov.b64 {%0, %1}, %2;" : "=f"(lo), "=f"(hi) : "l"(v));
}
static __device__ __forceinline__ float neg_inf() { return __int_as_float(0xff800000u); }

// ---------- build S ----------
__global__ void build_S_kernel(const float* __restrict__ vocab_emb) {
    int idx = blockIdx.x * blockDim.x + threadIdx.x;     // 0 .. VOCAB*32-1
    if (idx >= VOCAB * N_HEAD) return;
    int v = idx >> 5;
    int h = idx & 31;
    const float4* p = (const float4*)(vocab_emb + (size_t)v * N_EMBD + h * HEAD_DIM);
    float s = 0.f;
#pragma unroll
    for (int i = 0; i < 8; i++) {
        float4 f = p[i];
        s += (f.x + f.y) + (f.z + f.w);
    }
    g_S[v * 32 + h] = s;
}

// ---------- one thread's partial flash-softmax projection over v = off, off+8, ... ----------
static __device__ __forceinline__ void vocab_project_partial(
    const float* __restrict__ qrow,   // 32 floats (shared mem)
    float inv_t, int off,
    float& m_out, float& Z_out, float* __restrict__ acc_out /*32*/)
{
    u64 qp[16];
#pragma unroll
    for (int j = 0; j < 16; j++) qp[j] = pack2(qrow[2 * j], qrow[2 * j + 1]);

    float m = neg_inf();
    float Z = 0.f;
    u64 accp[16];
#pragma unroll
    for (int j = 0; j < 16; j++) accp[j] = 0ull;

    for (int v = off; v < VOCAB; v += 8) {
        const ulonglong2* __restrict__ c = (const ulonglong2*)(g_S + v * 32);
        u64 s[16];
#pragma unroll
        for (int j = 0; j < 8; j++) {
            ulonglong2 t2 = c[j];           // 128-bit load of 4 floats (2 packed pairs)
            s[2 * j]     = t2.x;
            s[2 * j + 1] = t2.y;
        }
        // logit = q . S[:,v]  via 4 independent packed chains
        u64 l0 = 0ull, l1 = 0ull, l2 = 0ull, l3 = 0ull;
#pragma unroll
        for (int j = 0; j < 16; j += 4) {
            FMA2(l0, qp[j + 0], s[j + 0], l0);
            FMA2(l1, qp[j + 1], s[j + 1], l1);
            FMA2(l2, qp[j + 2], s[j + 2], l2);
            FMA2(l3, qp[j + 3], s[j + 3], l3);
        }
        u64 la, lb, lc;
        ADD2(la, l0, l1);
        ADD2(lb, l2, l3);
        ADD2(lc, la, lb);
        float x0, x1;
        unpack2(lc, x0, x1);
        float l = (x0 + x1) * inv_t;

        if (l > m) {                         // rare (~log(n) triggers): rescale state
            float cs = __expf(m - l);
            m = l;
            Z *= cs;
            u64 c2 = pack2(cs, cs);
#pragma unroll
            for (int j = 0; j < 16; j++) MUL2(accp[j], accp[j], c2);
        }
        float w = __expf(l - m);
        Z += w;
        u64 w2 = pack2(w, w);
#pragma unroll
        for (int j = 0; j < 16; j++) FMA2(accp[j], w2, s[j], accp[j]);
    }

    m_out = m;
    Z_out = Z;
#pragma unroll
    for (int j = 0; j < 16; j++) unpack2(accp[j], acc_out[2 * j], acc_out[2 * j + 1]);
}

// ---------- fused main kernel: one block = one token (32 heads) ----------
extern "C" __global__ void __launch_bounds__(256, 1)
vocab_main_kernel(const float* __restrict__ x,
                  const float* __restrict__ W_ffn, const float* __restrict__ b_ffn,
                  const float* __restrict__ temps,
                  const float* __restrict__ W_ref, const float* __restrict__ b_ref,
                  const float* __restrict__ W_gate, const float* __restrict__ b_gate,
                  float* __restrict__ out)
{
    __shared__ float sm_x[32][32];
    __shared__ float sm_q[32][32];
    __shared__ float sm_vout[32][32];
    __shared__ float sm_m[8][32];
    __shared__ float sm_Z[8][32];
    __shared__ float sm_acc[8][32][33];   // +1 pad: conflict-free partial dump/merge

    const int bt  = blockIdx.x;
    const int t   = threadIdx.x;
    const int row = t & 31;   // head index
    const int off = t >> 5;   // vocab offset (warp id)

    // load this token's x (1024 floats)
    ((float4*)sm_x)[t] = ((const float4*)(x + (size_t)bt * N_EMBD))[t];
    __syncthreads();

    // ---- stage 1: q = x @ W_ffn^T + b_ffn (per head) ----
#pragma unroll
    for (int k = 0; k < 4; k++) {
        int o = (t << 2) + k;
        int n = o >> 5, d = o & 31;
        const float* wr = W_ffn + d * 32;
        float s = b_ffn[d];
#pragma unroll
        for (int h = 0; h < 32; h++) s = fmaf(sm_x[n][h], wr[h], s);
        sm_q[n][d] = s;
    }
    __syncthreads();

    const float inv_t = 1.0f / fmaxf(temps[row], TEMP_MIN);

    // ---- projection 1 ----
    {
        float m, Z, acc[32];
        vocab_project_partial(sm_q[row], inv_t, off, m, Z, acc);
        sm_m[off][row] = m;
        sm_Z[off][row] = Z;
#pragma unroll
        for (int h = 0; h < 32; h++) sm_acc[off][row][h] = acc[h];
    }
    __syncthreads();

    if (t < 32) {   // merge 8 partials per row, normalize -> sm_vout
        const int r = t;
        float M = neg_inf();
#pragma unroll
        for (int o = 0; o < 8; o++) M = fmaxf(M, sm_m[o][r]);
        float Zt = 0.f;
        float a[32];
#pragma unroll
        for (int h = 0; h < 32; h++) a[h] = 0.f;
#pragma unroll
        for (int o = 0; o < 8; o++) {
            float cs = __expf(sm_m[o][r] - M);
            Zt = fmaf(sm_Z[o][r], cs, Zt);
#pragma unroll
            for (int h = 0; h < 32; h++) a[h] = fmaf(sm_acc[o][r][h], cs, a[h]);
        }
        float iz = 1.0f / Zt;
#pragma unroll
        for (int h = 0; h < 32; h++) sm_vout[r][h] = a[h] * iz;
    }
    __syncthreads();

    // ---- gating stage: refined = vout*(1-g) + tanh(ref)*g ----
#pragma unroll
    for (int k = 0; k < 4; k++) {
        int o = (t << 2) + k;
        int n = o >> 5, d = o & 31;
        const float* wr = W_ref + d * 32;
        const float* wg = W_gate + d * 32;
        float sr = b_ref[d], sg = b_gate[d];
#pragma unroll
        for (int h = 0; h < 32; h++) {
            float xv = sm_x[n][h];
            sr = fmaf(xv, wr[h], sr);
            sg = fmaf(xv, wg[h], sg);
        }
        float refv = tanhf(sr);
        float g = 1.0f / (1.0f + __expf(-sg));
        sm_q[n][d] = sm_vout[n][d] * (1.0f - g) + refv * g;
    }
    __syncthreads();

    // ---- projection 2 ----
    {
        float m, Z, acc[32];
        vocab_project_partial(sm_q[row], inv_t, off, m, Z, acc);
        sm_m[off][row] = m;
        sm_Z[off][row] = Z;
#pragma unroll
        for (int h = 0; h < 32; h++) sm_acc[off][row][h] = acc[h];
    }
    __syncthreads();

    if (t < 32) {   // merge + write output
        const int r = t;
        float M = neg_inf();
#pragma unroll
        for (int o = 0; o < 8; o++) M = fmaxf(M, sm_m[o][r]);
        float Zt = 0.f;
        float a[32];
#pragma unroll
        for (int h = 0; h < 32; h++) a[h] = 0.f;
#pragma unroll
        for (int o = 0; o < 8; o++) {
            float cs = __expf(sm_m[o][r] - M);
            Zt = fmaf(sm_Z[o][r], cs, Zt);
#pragma unroll
            for (int h = 0; h < 32; h++) a[h] = fmaf(sm_acc[o][r][h], cs, a[h]);
        }
        float iz = 1.0f / Zt;
        float* orow = out + (size_t)bt * N_EMBD + r * 32;
#pragma unroll
        for (int h = 0; h < 32; h++) orow[h] = a[h] * iz;
    }
}

// ---------- launch ----------
extern "C" void kernel_launch(void* const* d_in, const int* in_sizes, int n_in,
                              void* d_out, int out_size) {
    const float* x         = (const float*)d_in[0];
    const float* vocab_emb = (const float*)d_in[1];
    const float* W_ffn     = (const float*)d_in[2];
    const float* b_ffn     = (const float*)d_in[3];
    const float* temps     = (const float*)d_in[4];
    const float* W_ref     = (const float*)d_in[5];
    const float* b_ref     = (const float*)d_in[6];
    const float* W_gate    = (const float*)d_in[7];
    const float* b_gate    = (const float*)d_in[8];
    float* out = (float*)d_out;

    build_S_kernel<<<(VOCAB * N_HEAD + 255) / 256, 256>>>(vocab_emb);
    vocab_main_kernel<<<NTOK, 256>>>(x, W_ffn, b_ffn, temps,
                                     W_ref, b_ref, W_gate, b_gate, out);
}

// round 4
// speedup vs baseline: 5.6337x; 5.6337x over previous
#include <cuda_runtime.h>
#include <cuda_bf16.h>
#include <cstdint>

#define N_HEAD   32
#define HEAD_DIM 32
#define N_EMBD   1024
#define VOCAB    32000
#define NTOK     128
#define NROWS    4096            // NTOK * N_HEAD
#define TEMP_MIN 0.1f
#define LOG2E    1.4426950408889634f

#define VT       128             // vocab columns per tile
#define NTILES   250             // 32000 / 128
#define NSPLIT   8
#define MTILES   32              // 4096 / 128

// padded tile layouts (conflict-free LDS for B-fragments)
#define SKV_ROW   80             // 32 bf16 (64B) + 16B pad
#define SKV_TILE  (VT * SKV_ROW)          // 10240 B
#define SHV_ROW   272            // 128 bf16 (256B) + 16B pad
#define SHV_TILE  (32 * SHV_ROW)          // 8704 B

// ---------------- global scratch ----------------------------------------------
__device__ __align__(256) char g_Skv[NTILES * SKV_TILE];   // [tile][v][ch] padded
__device__ __align__(256) char g_Shv[NTILES * SHV_TILE];   // [tile][ch][v] padded
__device__ __align__(256) __nv_bfloat16 g_Qhi[NROWS * 32];
__device__ __align__(256) __nv_bfloat16 g_Qlo[NROWS * 32];
__device__ __align__(256) float g_Opart[NSPLIT * NROWS * 32];
__device__ __align__(256) float g_Zpart[NSPLIT * NROWS];

// ---------------- helpers ------------------------------------------------------
__device__ __forceinline__ uint32_t smem_to_u32(const void* p) {
    uint32_t a;
    asm("{ .reg .u64 t; cvta.to.shared.u64 t, %1; cvt.u32.u64 %0, t; }" : "=r"(a) : "l"(p));
    return a;
}
#define CP_ASYNC16(dst_u32, src_ptr) \
    asm volatile("cp.async.cg.shared.global [%0], [%1], 16;" \
                 :: "r"(dst_u32), "l"(src_ptr) : "memory")
#define CP_COMMIT()  asm volatile("cp.async.commit_group;" ::: "memory")
#define CP_WAIT(n)   asm volatile("cp.async.wait_group %0;" :: "n"(n) : "memory")

__device__ __forceinline__ float ex2f(float x) {
    float r; asm("ex2.approx.f32 %0, %1;" : "=f"(r) : "f"(x)); return r;
}
__device__ __forceinline__ uint32_t pack_bf16x2(float lo, float hi) {
    uint32_t r;
    asm("cvt.rn.bf16x2.f32 %0, %1, %2;" : "=r"(r) : "f"(hi), "f"(lo));
    return r;
}
// D = A(16x16 bf16,row) @ B(16x8 bf16,col) + C   (f32 accum)
__device__ __forceinline__ void mma16816(float* d, const uint32_t* a, const uint32_t* b,
                                         const float* c) {
    asm volatile("mma.sync.aligned.m16n8k16.row.col.f32.bf16.bf16.f32 "
                 "{%0,%1,%2,%3}, {%4,%5,%6,%7}, {%8,%9}, {%10,%11,%12,%13};"
                 : "=f"(d[0]), "=f"(d[1]), "=f"(d[2]), "=f"(d[3])
                 : "r"(a[0]), "r"(a[1]), "r"(a[2]), "r"(a[3]),
                   "r"(b[0]), "r"(b[1]),
                   "f"(c[0]), "f"(c[1]), "f"(c[2]), "f"(c[3]));
}

// ---------------- kernel 1: build padded bf16 S tiles --------------------------
__global__ void build_S_tiles(const float* __restrict__ vocab_emb) {
    int gid = blockIdx.x * blockDim.x + threadIdx.x;       // VOCAB*32
    if (gid >= VOCAB * 32) return;
    int v = gid >> 5;
    int h = gid & 31;
    const float4* p = (const float4*)(vocab_emb + (size_t)v * N_EMBD + h * HEAD_DIM);
    float s = 0.f;
#pragma unroll
    for (int i = 0; i < 8; i++) { float4 f = p[i]; s += (f.x + f.y) + (f.z + f.w); }
    __nv_bfloat16 bv = __float2bfloat16_rn(s);
    int vt = v >> 7, vl = v & (VT - 1);
    *(__nv_bfloat16*)(g_Skv + (size_t)vt * SKV_TILE + vl * SKV_ROW + h * 2) = bv;
    *(__nv_bfloat16*)(g_Shv + (size_t)vt * SHV_TILE + h * SHV_ROW + vl * 2) = bv;
}

// ---------------- kernel 2: Q = FFN(x), bf16 hi/lo -----------------------------
__global__ void qbuild_kernel(const float* __restrict__ x,
                              const float* __restrict__ W, const float* __restrict__ b) {
    int row = blockIdx.x * blockDim.x + threadIdx.x;
    if (row >= NROWS) return;
    float xr[32];
    const float4* xp = (const float4*)(x + (size_t)row * 32);
#pragma unroll
    for (int i = 0; i < 8; i++) { float4 f = xp[i]; xr[4*i]=f.x; xr[4*i+1]=f.y; xr[4*i+2]=f.z; xr[4*i+3]=f.w; }
#pragma unroll 4
    for (int d = 0; d < 32; d++) {
        const float* w = W + d * 32;
        float s = b[d];
#pragma unroll
        for (int h = 0; h < 32; h++) s = fmaf(xr[h], w[h], s);
        __nv_bfloat16 hi = __float2bfloat16_rn(s);
        g_Qhi[row * 32 + d] = hi;
        g_Qlo[row * 32 + d] = __float2bfloat16_rn(s - __bfloat162float(hi));
    }
}

// ---------------- flash kernel: warp-MMA, register-fused softmax ---------------
// grid = MTILES*NSPLIT.  blockDim = 256 (8 warps, M=16 rows each).
__global__ void __launch_bounds__(256, 2)
flash_kernel(const float* __restrict__ temps) {
    __shared__ __align__(16) char skv[2][SKV_TILE];
    __shared__ __align__(16) char shv[2][SHV_TILE];

    const int tid = threadIdx.x, w = tid >> 5, lane = tid & 31;
    const int gid = lane >> 2, tig = lane & 3;
    const int m = blockIdx.x & (MTILES - 1), s = blockIdx.x >> 5;
    const int rw0 = m * 128 + w * 16;                 // first global row of this warp
    const int t0 = (s * NTILES) / NSPLIT, t1 = ((s + 1) * NTILES) / NSPLIT;
    const int nT = t1 - t0;

    const uint32_t skv_b[2] = { smem_to_u32(skv[0]), smem_to_u32(skv[1]) };
    const uint32_t shv_b[2] = { smem_to_u32(shv[0]), smem_to_u32(shv[1]) };

    // ---- persistent Q fragments (A of GEMM1): m16k16, ksteps 0,1, hi/lo ----
    uint32_t qhi[2][4], qlo[2][4];
#pragma unroll
    for (int ks = 0; ks < 2; ks++) {
        int c0 = ks * 16 + 2 * tig;
        qhi[ks][0] = *(const uint32_t*)&g_Qhi[(size_t)(rw0 + gid)     * 32 + c0];
        qhi[ks][1] = *(const uint32_t*)&g_Qhi[(size_t)(rw0 + gid + 8) * 32 + c0];
        qhi[ks][2] = *(const uint32_t*)&g_Qhi[(size_t)(rw0 + gid)     * 32 + c0 + 8];
        qhi[ks][3] = *(const uint32_t*)&g_Qhi[(size_t)(rw0 + gid + 8) * 32 + c0 + 8];
        qlo[ks][0] = *(const uint32_t*)&g_Qlo[(size_t)(rw0 + gid)     * 32 + c0];
        qlo[ks][1] = *(const uint32_t*)&g_Qlo[(size_t)(rw0 + gid + 8) * 32 + c0];
        qlo[ks][2] = *(const uint32_t*)&g_Qlo[(size_t)(rw0 + gid)     * 32 + c0 + 8];
        qlo[ks][3] = *(const uint32_t*)&g_Qlo[(size_t)(rw0 + gid + 8) * 32 + c0 + 8];
    }

    // softmax scales for this thread's two row groups (head = row % 32)
    const int h0 = ((w & 1) * 16 + gid);
    const float s2a = LOG2E / fmaxf(temps[h0],     TEMP_MIN);
    const float s2b = LOG2E / fmaxf(temps[h0 + 8], TEMP_MIN);

    float outacc[4][4];
#pragma unroll
    for (int n2 = 0; n2 < 4; n2++)
#pragma unroll
        for (int k = 0; k < 4; k++) outacc[n2][k] = 0.f;
    float zacc0 = 0.f, zacc1 = 0.f;

    // ---- cp.async tile copy helper (raw bytes, layouts identical) ----
    // SKV_TILE = 10240 B = 640 x 16B chunks; SHV_TILE = 8704 B = 544 x 16B chunks.
    auto issue_tile = [&](int stg, int vt) {
        const char* gk = g_Skv + (size_t)vt * SKV_TILE;
        const char* gh = g_Shv + (size_t)vt * SHV_TILE;
        uint32_t dk = skv_b[stg], dh = shv_b[stg];
        CP_ASYNC16(dk + tid * 16,         gk + tid * 16);
        CP_ASYNC16(dk + 4096 + tid * 16,  gk + 4096 + tid * 16);
        if (tid < 128) CP_ASYNC16(dk + 8192 + tid * 16, gk + 8192 + tid * 16);
        CP_ASYNC16(dh + tid * 16,         gh + tid * 16);
        CP_ASYNC16(dh + 4096 + tid * 16,  gh + 4096 + tid * 16);   // covers up to 8192
        if (tid < 32) CP_ASYNC16(dh + 8192 + tid * 16, gh + 8192 + tid * 16);  // 8192..8704
        CP_COMMIT();
    };

    issue_tile(0, t0);

    for (int i = 0; i < nT; i++) {
        const int stg = i & 1;
        __syncthreads();                       // stage (i+1)&1 fully consumed
        if (i + 1 < nT) issue_tile((i + 1) & 1, t0 + i + 1);
        if (i + 1 < nT) { CP_WAIT(1); } else { CP_WAIT(0); }
        __syncthreads();                       // stage stg visible to all

        const uint32_t kv = skv_b[stg];
        const uint32_t hv = shv_b[stg];

#pragma unroll 2
        for (int c0 = 0; c0 < VT; c0 += 16) {  // 16-vocab chunk
            // B-fragments for GEMM1: cols c0+8j+gid, both ksteps
            uint32_t bA[2][2][2];
#pragma unroll
            for (int j = 0; j < 2; j++) {
                uint32_t rbase = kv + (uint32_t)((c0 + j * 8 + gid) * SKV_ROW + tig * 4);
#pragma unroll
                for (int ks = 0; ks < 2; ks++) {
                    asm volatile("ld.shared.b32 %0, [%1];" : "=r"(bA[j][ks][0]) : "r"(rbase + ks * 32));
                    asm volatile("ld.shared.b32 %0, [%1];" : "=r"(bA[j][ks][1]) : "r"(rbase + ks * 32 + 16));
                }
            }
            // logits chunk: d[j] = Qhi@S + Qlo@S
            float d0[4] = {0.f, 0.f, 0.f, 0.f}, d1[4] = {0.f, 0.f, 0.f, 0.f};
            mma16816(d0, qhi[0], bA[0][0], d0);
            mma16816(d0, qhi[1], bA[0][1], d0);
            mma16816(d0, qlo[0], bA[0][0], d0);
            mma16816(d0, qlo[1], bA[0][1], d0);
            mma16816(d1, qhi[0], bA[1][0], d1);
            mma16816(d1, qhi[1], bA[1][1], d1);
            mma16816(d1, qlo[0], bA[1][0], d1);
            mma16816(d1, qlo[1], bA[1][1], d1);

            // exp (fixed reference 0) + Z accumulation
            float e00 = ex2f(d0[0] * s2a), e01 = ex2f(d0[1] * s2a);
            float e02 = ex2f(d0[2] * s2b), e03 = ex2f(d0[3] * s2b);
            float e10 = ex2f(d1[0] * s2a), e11 = ex2f(d1[1] * s2a);
            float e12 = ex2f(d1[2] * s2b), e13 = ex2f(d1[3] * s2b);
            zacc0 += (e00 + e01) + (e10 + e11);
            zacc1 += (e02 + e03) + (e12 + e13);

            // repack as A-fragment of GEMM2 (m16k16 over these 16 vocab)
            uint32_t pa[4];
            pa[0] = pack_bf16x2(e00, e01);
            pa[1] = pack_bf16x2(e02, e03);
            pa[2] = pack_bf16x2(e10, e11);
            pa[3] = pack_bf16x2(e12, e13);

            // GEMM2: out[16,32] += P_chunk @ S^T_chunk
#pragma unroll
            for (int n2 = 0; n2 < 4; n2++) {
                uint32_t rbase = hv + (uint32_t)((n2 * 8 + gid) * SHV_ROW + (c0 + 2 * tig) * 2);
                uint32_t bB[2];
                asm volatile("ld.shared.b32 %0, [%1];" : "=r"(bB[0]) : "r"(rbase));
                asm volatile("ld.shared.b32 %0, [%1];" : "=r"(bB[1]) : "r"(rbase + 16));
                mma16816(outacc[n2], pa, bB, outacc[n2]);
            }
        }
    }

    // ---- epilogue: reduce Z across the 4 lanes sharing a row, write partials ----
    zacc0 += __shfl_xor_sync(0xFFFFFFFFu, zacc0, 1);
    zacc0 += __shfl_xor_sync(0xFFFFFFFFu, zacc0, 2);
    zacc1 += __shfl_xor_sync(0xFFFFFFFFu, zacc1, 1);
    zacc1 += __shfl_xor_sync(0xFFFFFFFFu, zacc1, 2);

    const int r0g = rw0 + gid, r1g = rw0 + gid + 8;
    if (tig == 0) {
        g_Zpart[s * NROWS + r0g] = zacc0;
        g_Zpart[s * NROWS + r1g] = zacc1;
    }
#pragma unroll
    for (int n2 = 0; n2 < 4; n2++) {
        int col = n2 * 8 + 2 * tig;
        *(float2*)&g_Opart[((size_t)s * NROWS + r0g) * 32 + col] =
            make_float2(outacc[n2][0], outacc[n2][1]);
        *(float2*)&g_Opart[((size_t)s * NROWS + r1g) * 32 + col] =
            make_float2(outacc[n2][2], outacc[n2][3]);
    }
}

// ---------------- merge partials + gate -> Q2 ----------------------------------
__global__ void merge_gate_kernel(const float* __restrict__ x,
                                  const float* __restrict__ W_ref, const float* __restrict__ b_ref,
                                  const float* __restrict__ W_gate, const float* __restrict__ b_gate) {
    int gid = blockIdx.x * blockDim.x + threadIdx.x;
    if (gid >= NROWS * 32) return;
    int row = gid >> 5, d = gid & 31;
    float O = 0.f, Z = 0.f;
#pragma unroll
    for (int s = 0; s < NSPLIT; s++) {
        O += g_Opart[((size_t)s * NROWS + row) * 32 + d];
        Z += g_Zpart[s * NROWS + row];
    }
    float vout = O / Z;
    const float* xr = x + (size_t)row * 32;
    const float* wr = W_ref + d * 32;
    const float* wg = W_gate + d * 32;
    float sr = b_ref[d], sg = b_gate[d];
#pragma unroll
    for (int h = 0; h < 32; h++) { float xv = xr[h]; sr = fmaf(xv, wr[h], sr); sg = fmaf(xv, wg[h], sg); }
    float refv = tanhf(sr);
    float g = 1.0f / (1.0f + __expf(-sg));
    float q2 = vout * (1.0f - g) + refv * g;
    __nv_bfloat16 hi = __float2bfloat16_rn(q2);
    g_Qhi[row * 32 + d] = hi;
    g_Qlo[row * 32 + d] = __float2bfloat16_rn(q2 - __bfloat162float(hi));
}

// ---------------- final merge -> out -------------------------------------------
__global__ void final_kernel(float* __restrict__ out) {
    int gid = blockIdx.x * blockDim.x + threadIdx.x;
    if (gid >= NROWS * 32) return;
    int row = gid >> 5, d = gid & 31;
    float O = 0.f, Z = 0.f;
#pragma unroll
    for (int s = 0; s < NSPLIT; s++) {
        O += g_Opart[((size_t)s * NROWS + row) * 32 + d];
        Z += g_Zpart[s * NROWS + row];
    }
    out[(size_t)row * 32 + d] = O / Z;
}

// ---------------- launch -------------------------------------------------------
extern "C" void kernel_launch(void* const* d_in, const int* in_sizes, int n_in,
                              void* d_out, int out_size) {
    const float* x         = (const float*)d_in[0];
    const float* vocab_emb = (const float*)d_in[1];
    const float* W_ffn     = (const float*)d_in[2];
    const float* b_ffn     = (const float*)d_in[3];
    const float* temps     = (const float*)d_in[4];
    const float* W_ref     = (const float*)d_in[5];
    const float* b_ref     = (const float*)d_in[6];
    const float* W_gate    = (const float*)d_in[7];
    const float* b_gate    = (const float*)d_in[8];
    float* out = (float*)d_out;

    build_S_tiles<<<(VOCAB * 32 + 255) / 256, 256>>>(vocab_emb);
    qbuild_kernel<<<(NROWS + 255) / 256, 256>>>(x, W_ffn, b_ffn);
    flash_kernel<<<MTILES * NSPLIT, 256>>>(temps);
    merge_gate_kernel<<<(NROWS * 32 + 255) / 256, 256>>>(x, W_ref, b_ref, W_gate, b_gate);
    flash_kernel<<<MTILES * NSPLIT, 256>>>(temps);
    final_kernel<<<(NROWS * 32 + 255) / 256, 256>>>(out);
}

// round 5
// speedup vs baseline: 6.8330x; 1.2129x over previous
#include <cuda_runtime.h>
#include <cuda_bf16.h>
#include <cstdint>

#define N_HEAD   32
#define HEAD_DIM 32
#define N_EMBD   1024
#define VOCAB    32000
#define NTOK     128
#define NROWS    4096            // NTOK * N_HEAD
#define TEMP_MIN 0.1f
#define LOG2E    1.4426950408889634f

#define VT       128             // vocab columns per tile
#define NTILES   250             // 32000 / 128
#define NSPLIT   8
#define MTILES   32              // 4096 / 128

// padded tile layouts (conflict-free LDS for B-fragments)
#define SKV_ROW   80             // 32 bf16 (64B) + 16B pad
#define SKV_TILE  (VT * SKV_ROW)          // 10240 B
#define SHV_ROW   272            // 128 bf16 (256B) + 16B pad
#define SHV_TILE  (32 * SHV_ROW)          // 8704 B

// ---------------- global scratch ----------------------------------------------
__device__ __align__(256) char g_Skv[NTILES * SKV_TILE];   // [tile][v][ch] padded
__device__ __align__(256) char g_Shv[NTILES * SHV_TILE];   // [tile][ch][v] padded
__device__ __align__(256) __nv_bfloat16 g_Qhi[NROWS * 32];
__device__ __align__(256) __nv_bfloat16 g_Qlo[NROWS * 32];
__device__ __align__(256) float g_Opart[NSPLIT * NROWS * 32];
__device__ __align__(256) float g_Zpart[NSPLIT * NROWS];

// ---------------- helpers ------------------------------------------------------
__device__ __forceinline__ uint32_t smem_to_u32(const void* p) {
    uint32_t a;
    asm("{ .reg .u64 t; cvta.to.shared.u64 t, %1; cvt.u32.u64 %0, t; }" : "=r"(a) : "l"(p));
    return a;
}
#define CP_ASYNC16(dst_u32, src_ptr) \
    asm volatile("cp.async.cg.shared.global [%0], [%1], 16;" \
                 :: "r"(dst_u32), "l"(src_ptr) : "memory")
#define CP_COMMIT()  asm volatile("cp.async.commit_group;" ::: "memory")
#define CP_WAIT(n)   asm volatile("cp.async.wait_group %0;" :: "n"(n) : "memory")

__device__ __forceinline__ float ex2f(float x) {
    float r; asm("ex2.approx.f32 %0, %1;" : "=f"(r) : "f"(x)); return r;
}
__device__ __forceinline__ uint32_t pack_bf16x2(float lo, float hi) {
    uint32_t r;
    asm("cvt.rn.bf16x2.f32 %0, %1, %2;" : "=r"(r) : "f"(hi), "f"(lo));
    return r;
}
// D = A(16x16 bf16,row) @ B(16x8 bf16,col) + C   (f32 accum)
__device__ __forceinline__ void mma16816(float* d, const uint32_t* a, const uint32_t* b,
                                         const float* c) {
    asm volatile("mma.sync.aligned.m16n8k16.row.col.f32.bf16.bf16.f32 "
                 "{%0,%1,%2,%3}, {%4,%5,%6,%7}, {%8,%9}, {%10,%11,%12,%13};"
                 : "=f"(d[0]), "=f"(d[1]), "=f"(d[2]), "=f"(d[3])
                 : "r"(a[0]), "r"(a[1]), "r"(a[2]), "r"(a[3]),
                   "r"(b[0]), "r"(b[1]),
                   "f"(c[0]), "f"(c[1]), "f"(c[2]), "f"(c[3]));
}

// ---------------- kernel 1: build bf16 S tiles (smem transpose, coalesced) -----
// one block per vocab tile (128 v x 32 h), 256 threads
__global__ void __launch_bounds__(256)
build_S_tiles(const float* __restrict__ vocab_emb) {
    __shared__ __nv_bfloat16 T[128][34];         // +2 pad (68B row, 4B aligned)
    const int t = threadIdx.x, vt = blockIdx.x;
    const int v0 = vt * VT;

#pragma unroll
    for (int k = 0; k < 16; k++) {
        int idx = k * 256 + t;                   // 0..4095
        int v = idx >> 5, h = idx & 31;
        const float4* p = (const float4*)(vocab_emb + (size_t)(v0 + v) * N_EMBD + h * HEAD_DIM);
        float s = 0.f;
#pragma unroll
        for (int i = 0; i < 8; i++) { float4 f = p[i]; s += (f.x + f.y) + (f.z + f.w); }
        T[v][h] = __float2bfloat16_rn(s);
    }
    __syncthreads();

    // Skv: [v][h] rows of 64B, contiguous u32 stores
    char* gk = g_Skv + (size_t)vt * SKV_TILE;
#pragma unroll
    for (int k = 0; k < 8; k++) {
        int idx = k * 256 + t;                   // 0..2047: v=idx>>4, c=idx&15
        int v = idx >> 4, c = idx & 15;
        uint32_t val = *(const uint32_t*)&T[v][2 * c];
        *(uint32_t*)(gk + v * SKV_ROW + c * 4) = val;
    }
    // Shv: [h][v] rows of 256B, contiguous u32 stores (transpose read from smem)
    char* gh = g_Shv + (size_t)vt * SHV_TILE;
#pragma unroll
    for (int k = 0; k < 8; k++) {
        int idx = k * 256 + t;                   // 0..2047: h=idx>>6, c=idx&63
        int h = idx >> 6, c = idx & 63;
        uint16_t a = *(const uint16_t*)&T[2 * c][h];
        uint16_t b = *(const uint16_t*)&T[2 * c + 1][h];
        uint32_t val = ((uint32_t)b << 16) | (uint32_t)a;
        *(uint32_t*)(gh + h * SHV_ROW + c * 4) = val;
    }
}

// ---------------- kernel 2: Q = FFN(x), bf16 hi/lo (smem W, thread per (row,d)) -
__global__ void __launch_bounds__(256)
qbuild_kernel(const float* __restrict__ x,
              const float* __restrict__ W, const float* __restrict__ b) {
    __shared__ float sW[32 * 33];
    __shared__ float sx[8][32];
    const int t = threadIdx.x;
    const int row0 = blockIdx.x * 8;
#pragma unroll
    for (int k = 0; k < 4; k++) {
        int i = k * 256 + t;                     // 0..1023
        sW[(i >> 5) * 33 + (i & 31)] = W[i];
    }
    const int rl = t >> 5, d = t & 31;
    const int row = row0 + rl;
    sx[rl][d] = x[(size_t)row * 32 + d];
    __syncthreads();

    float s = b[d];
    const float* wr = sW + d * 33;
#pragma unroll
    for (int h = 0; h < 32; h++) s = fmaf(sx[rl][h], wr[h], s);
    __nv_bfloat16 hi = __float2bfloat16_rn(s);
    g_Qhi[row * 32 + d] = hi;
    g_Qlo[row * 32 + d] = __float2bfloat16_rn(s - __bfloat162float(hi));
}

// ---------------- flash kernel: warp-MMA, register-fused softmax ---------------
// grid = MTILES*NSPLIT.  blockDim = 256 (8 warps, M=16 rows each).
__global__ void __launch_bounds__(256, 2)
flash_kernel(const float* __restrict__ temps) {
    __shared__ __align__(16) char skv[2][SKV_TILE];
    __shared__ __align__(16) char shv[2][SHV_TILE];

    const int tid = threadIdx.x, w = tid >> 5, lane = tid & 31;
    const int gid = lane >> 2, tig = lane & 3;
    const int m = blockIdx.x & (MTILES - 1), s = blockIdx.x >> 5;
    const int rw0 = m * 128 + w * 16;                 // first global row of this warp
    const int t0 = (s * NTILES) / NSPLIT, t1 = ((s + 1) * NTILES) / NSPLIT;
    const int nT = t1 - t0;

    const uint32_t skv_b[2] = { smem_to_u32(skv[0]), smem_to_u32(skv[1]) };
    const uint32_t shv_b[2] = { smem_to_u32(shv[0]), smem_to_u32(shv[1]) };

    // ---- persistent Q fragments (A of GEMM1): m16k16, ksteps 0,1, hi/lo ----
    uint32_t qhi[2][4], qlo[2][4];
#pragma unroll
    for (int ks = 0; ks < 2; ks++) {
        int c0 = ks * 16 + 2 * tig;
        qhi[ks][0] = *(const uint32_t*)&g_Qhi[(size_t)(rw0 + gid)     * 32 + c0];
        qhi[ks][1] = *(const uint32_t*)&g_Qhi[(size_t)(rw0 + gid + 8) * 32 + c0];
        qhi[ks][2] = *(const uint32_t*)&g_Qhi[(size_t)(rw0 + gid)     * 32 + c0 + 8];
        qhi[ks][3] = *(const uint32_t*)&g_Qhi[(size_t)(rw0 + gid + 8) * 32 + c0 + 8];
        qlo[ks][0] = *(const uint32_t*)&g_Qlo[(size_t)(rw0 + gid)     * 32 + c0];
        qlo[ks][1] = *(const uint32_t*)&g_Qlo[(size_t)(rw0 + gid + 8) * 32 + c0];
        qlo[ks][2] = *(const uint32_t*)&g_Qlo[(size_t)(rw0 + gid)     * 32 + c0 + 8];
        qlo[ks][3] = *(const uint32_t*)&g_Qlo[(size_t)(rw0 + gid + 8) * 32 + c0 + 8];
    }

    // softmax scales for this thread's two row groups (head = row % 32)
    const int h0 = ((w & 1) * 16 + gid);
    const float s2a = LOG2E / fmaxf(temps[h0],     TEMP_MIN);
    const float s2b = LOG2E / fmaxf(temps[h0 + 8], TEMP_MIN);

    float outacc[4][4];
#pragma unroll
    for (int n2 = 0; n2 < 4; n2++)
#pragma unroll
        for (int k = 0; k < 4; k++) outacc[n2][k] = 0.f;
    float zacc0 = 0.f, zacc1 = 0.f;

    // ---- cp.async tile copy helper ----
    auto issue_tile = [&](int stg, int vt) {
        const char* gk = g_Skv + (size_t)vt * SKV_TILE;
        const char* gh = g_Shv + (size_t)vt * SHV_TILE;
        uint32_t dk = skv_b[stg], dh = shv_b[stg];
        CP_ASYNC16(dk + tid * 16,         gk + tid * 16);
        CP_ASYNC16(dk + 4096 + tid * 16,  gk + 4096 + tid * 16);
        if (tid < 128) CP_ASYNC16(dk + 8192 + tid * 16, gk + 8192 + tid * 16);
        CP_ASYNC16(dh + tid * 16,         gh + tid * 16);
        CP_ASYNC16(dh + 4096 + tid * 16,  gh + 4096 + tid * 16);
        if (tid < 32) CP_ASYNC16(dh + 8192 + tid * 16, gh + 8192 + tid * 16);
        CP_COMMIT();
    };

    issue_tile(0, t0);

    for (int i = 0; i < nT; i++) {
        const int stg = i & 1;
        __syncthreads();                       // stage (i+1)&1 fully consumed
        if (i + 1 < nT) issue_tile((i + 1) & 1, t0 + i + 1);
        if (i + 1 < nT) { CP_WAIT(1); } else { CP_WAIT(0); }
        __syncthreads();                       // stage stg visible to all

        const uint32_t kv = skv_b[stg];
        const uint32_t hv = shv_b[stg];

#pragma unroll 2
        for (int c0 = 0; c0 < VT; c0 += 16) {  // 16-vocab chunk
            uint32_t bA[2][2][2];
#pragma unroll
            for (int j = 0; j < 2; j++) {
                uint32_t rbase = kv + (uint32_t)((c0 + j * 8 + gid) * SKV_ROW + tig * 4);
#pragma unroll
                for (int ks = 0; ks < 2; ks++) {
                    asm volatile("ld.shared.b32 %0, [%1];" : "=r"(bA[j][ks][0]) : "r"(rbase + ks * 32));
                    asm volatile("ld.shared.b32 %0, [%1];" : "=r"(bA[j][ks][1]) : "r"(rbase + ks * 32 + 16));
                }
            }
            float d0[4] = {0.f, 0.f, 0.f, 0.f}, d1[4] = {0.f, 0.f, 0.f, 0.f};
            mma16816(d0, qhi[0], bA[0][0], d0);
            mma16816(d0, qhi[1], bA[0][1], d0);
            mma16816(d0, qlo[0], bA[0][0], d0);
            mma16816(d0, qlo[1], bA[0][1], d0);
            mma16816(d1, qhi[0], bA[1][0], d1);
            mma16816(d1, qhi[1], bA[1][1], d1);
            mma16816(d1, qlo[0], bA[1][0], d1);
            mma16816(d1, qlo[1], bA[1][1], d1);

            float e00 = ex2f(d0[0] * s2a), e01 = ex2f(d0[1] * s2a);
            float e02 = ex2f(d0[2] * s2b), e03 = ex2f(d0[3] * s2b);
            float e10 = ex2f(d1[0] * s2a), e11 = ex2f(d1[1] * s2a);
            float e12 = ex2f(d1[2] * s2b), e13 = ex2f(d1[3] * s2b);
            zacc0 += (e00 + e01) + (e10 + e11);
            zacc1 += (e02 + e03) + (e12 + e13);

            uint32_t pa[4];
            pa[0] = pack_bf16x2(e00, e01);
            pa[1] = pack_bf16x2(e02, e03);
            pa[2] = pack_bf16x2(e10, e11);
            pa[3] = pack_bf16x2(e12, e13);

#pragma unroll
            for (int n2 = 0; n2 < 4; n2++) {
                uint32_t rbase = hv + (uint32_t)((n2 * 8 + gid) * SHV_ROW + (c0 + 2 * tig) * 2);
                uint32_t bB[2];
                asm volatile("ld.shared.b32 %0, [%1];" : "=r"(bB[0]) : "r"(rbase));
                asm volatile("ld.shared.b32 %0, [%1];" : "=r"(bB[1]) : "r"(rbase + 16));
                mma16816(outacc[n2], pa, bB, outacc[n2]);
            }
        }
    }

    // ---- epilogue ----
    zacc0 += __shfl_xor_sync(0xFFFFFFFFu, zacc0, 1);
    zacc0 += __shfl_xor_sync(0xFFFFFFFFu, zacc0, 2);
    zacc1 += __shfl_xor_sync(0xFFFFFFFFu, zacc1, 1);
    zacc1 += __shfl_xor_sync(0xFFFFFFFFu, zacc1, 2);

    const int r0g = rw0 + gid, r1g = rw0 + gid + 8;
    if (tig == 0) {
        g_Zpart[s * NROWS + r0g] = zacc0;
        g_Zpart[s * NROWS + r1g] = zacc1;
    }
#pragma unroll
    for (int n2 = 0; n2 < 4; n2++) {
        int col = n2 * 8 + 2 * tig;
        *(float2*)&g_Opart[((size_t)s * NROWS + r0g) * 32 + col] =
            make_float2(outacc[n2][0], outacc[n2][1]);
        *(float2*)&g_Opart[((size_t)s * NROWS + r1g) * 32 + col] =
            make_float2(outacc[n2][2], outacc[n2][3]);
    }
}

// ---------------- merge partials + gate -> Q2 (smem W, 8 rows/block) -----------
__global__ void __launch_bounds__(256)
merge_gate_kernel(const float* __restrict__ x,
                  const float* __restrict__ W_ref, const float* __restrict__ b_ref,
                  const float* __restrict__ W_gate, const float* __restrict__ b_gate) {
    __shared__ float sWr[32 * 33], sWg[32 * 33];
    __shared__ float sx[8][32];
    const int t = threadIdx.x;
    const int row0 = blockIdx.x * 8;
#pragma unroll
    for (int k = 0; k < 4; k++) {
        int i = k * 256 + t;
        int di = (i >> 5) * 33 + (i & 31);
        sWr[di] = W_ref[i];
        sWg[di] = W_gate[i];
    }
    const int rl = t >> 5, d = t & 31;
    const int row = row0 + rl;
    sx[rl][d] = x[(size_t)row * 32 + d];

    float O = 0.f, Z = 0.f;
#pragma unroll
    for (int s = 0; s < NSPLIT; s++) {
        O += g_Opart[((size_t)s * NROWS + row) * 32 + d];
        Z += g_Zpart[s * NROWS + row];
    }
    float vout = O / Z;
    __syncthreads();

    float sr = b_ref[d], sg = b_gate[d];
    const float* wr = sWr + d * 33;
    const float* wg = sWg + d * 33;
#pragma unroll
    for (int h = 0; h < 32; h++) {
        float xv = sx[rl][h];
        sr = fmaf(xv, wr[h], sr);
        sg = fmaf(xv, wg[h], sg);
    }
    float refv = tanhf(sr);
    float g = 1.0f / (1.0f + __expf(-sg));
    float q2 = vout * (1.0f - g) + refv * g;
    __nv_bfloat16 hi = __float2bfloat16_rn(q2);
    g_Qhi[row * 32 + d] = hi;
    g_Qlo[row * 32 + d] = __float2bfloat16_rn(q2 - __bfloat162float(hi));
}

// ---------------- final merge -> out (vectorized) ------------------------------
__global__ void final_kernel(float* __restrict__ out) {
    int gid = blockIdx.x * blockDim.x + threadIdx.x;      // NROWS*8
    if (gid >= NROWS * 8) return;
    int row = gid >> 3, c4 = (gid & 7) * 4;
    float4 O = make_float4(0.f, 0.f, 0.f, 0.f);
    float Z = 0.f;
#pragma unroll
    for (int s = 0; s < NSPLIT; s++) {
        float4 o = *(const float4*)&g_Opart[((size_t)s * NROWS + row) * 32 + c4];
        O.x += o.x; O.y += o.y; O.z += o.z; O.w += o.w;
        Z += g_Zpart[s * NROWS + row];
    }
    float iz = 1.0f / Z;
    *(float4*)&out[(size_t)row * 32 + c4] =
        make_float4(O.x * iz, O.y * iz, O.z * iz, O.w * iz);
}

// ---------------- launch -------------------------------------------------------
extern "C" void kernel_launch(void* const* d_in, const int* in_sizes, int n_in,
                              void* d_out, int out_size) {
    const float* x         = (const float*)d_in[0];
    const float* vocab_emb = (const float*)d_in[1];
    const float* W_ffn     = (const float*)d_in[2];
    const float* b_ffn     = (const float*)d_in[3];
    const float* temps     = (const float*)d_in[4];
    const float* W_ref     = (const float*)d_in[5];
    const float* b_ref     = (const float*)d_in[6];
    const float* W_gate    = (const float*)d_in[7];
    const float* b_gate    = (const float*)d_in[8];
    float* out = (float*)d_out;

    build_S_tiles<<<NTILES, 256>>>(vocab_emb);
    qbuild_kernel<<<NROWS / 8, 256>>>(x, W_ffn, b_ffn);
    flash_kernel<<<MTILES * NSPLIT, 256>>>(temps);
    merge_gate_kernel<<<NROWS / 8, 256>>>(x, W_ref, b_ref, W_gate, b_gate);
    flash_kernel<<<MTILES * NSPLIT, 256>>>(temps);
    final_kernel<<<(NROWS * 8 + 255) / 256, 256>>>(out);
}

// round 6
// speedup vs baseline: 9.3841x; 1.3733x over previous
#include <cuda_runtime.h>
#include <cuda_fp16.h>
#include <cstdint>

#define N_HEAD   32
#define HEAD_DIM 32
#define N_EMBD   1024
#define VOCAB    32000
#define NTOK     128
#define NROWS    4096            // NTOK * N_HEAD
#define TEMP_MIN 0.1f
#define LOG2E    1.4426950408889634f

#define VT       128             // vocab columns per tile
#define NTILES   250             // 32000 / 128
#define NSPLIT   9
#define MTILES   32              // 4096 / 128

// padded tile layouts (conflict-free LDS for B-fragments)
#define SKV_ROW   80             // 32 f16 (64B) + 16B pad
#define SKV_TILE  (VT * SKV_ROW)          // 10240 B
#define SHV_ROW   272            // 128 f16 (256B) + 16B pad
#define SHV_NROW  40             // 32 data rows + ones row (32) + 7 zero rows
#define SHV_TILE  (SHV_NROW * SHV_ROW)    // 10880 B

// ---------------- global scratch ----------------------------------------------
__device__ __align__(256) char g_Skv[NTILES * SKV_TILE];   // [tile][v][ch] f16 padded
__device__ __align__(256) char g_Shv[NTILES * SHV_TILE];   // [tile][ch][v] f16 padded
__device__ __align__(256) __half g_Qh[NROWS * 32];
__device__ __align__(256) float g_Opart[NSPLIT * NROWS * 32];
__device__ __align__(256) float g_Zpart[NSPLIT * NROWS];

// ---------------- helpers ------------------------------------------------------
__device__ __forceinline__ uint32_t smem_to_u32(const void* p) {
    uint32_t a;
    asm("{ .reg .u64 t; cvta.to.shared.u64 t, %1; cvt.u32.u64 %0, t; }" : "=r"(a) : "l"(p));
    return a;
}
#define CP_ASYNC16(dst_u32, src_ptr) \
    asm volatile("cp.async.cg.shared.global [%0], [%1], 16;" \
                 :: "r"(dst_u32), "l"(src_ptr) : "memory")
#define CP_COMMIT()  asm volatile("cp.async.commit_group;" ::: "memory")
#define CP_WAIT(n)   asm volatile("cp.async.wait_group %0;" :: "n"(n) : "memory")

// pack two f32 into f16x2 (first asm operand -> high half), then exp2 both
__device__ __forceinline__ uint32_t cvt_f16x2(float lo, float hi) {
    uint32_t r;
    asm("cvt.rn.f16x2.f32 %0, %1, %2;" : "=r"(r) : "f"(hi), "f"(lo));
    return r;
}
__device__ __forceinline__ uint32_t ex2_f16x2(uint32_t x) {
    uint32_t r;
    asm("ex2.approx.f16x2 %0, %1;" : "=r"(r) : "r"(x));
    return r;
}
// D = A(16x16 f16,row) @ B(16x8 f16,col) + C   (f32 accum)
__device__ __forceinline__ void mma16816h(float* d, const uint32_t* a, const uint32_t* b,
                                          const float* c) {
    asm volatile("mma.sync.aligned.m16n8k16.row.col.f32.f16.f16.f32 "
                 "{%0,%1,%2,%3}, {%4,%5,%6,%7}, {%8,%9}, {%10,%11,%12,%13};"
                 : "=f"(d[0]), "=f"(d[1]), "=f"(d[2]), "=f"(d[3])
                 : "r"(a[0]), "r"(a[1]), "r"(a[2]), "r"(a[3]),
                   "r"(b[0]), "r"(b[1]),
                   "f"(c[0]), "f"(c[1]), "f"(c[2]), "f"(c[3]));
}

// ---------------- kernel 1: build f16 S tiles (smem transpose, coalesced) ------
// one block per vocab tile (128 v x 32 h), 256 threads
__global__ void __launch_bounds__(256)
build_S_tiles(const float* __restrict__ vocab_emb) {
    __shared__ __half T[128][34];                // +2 pad
    const int t = threadIdx.x, vt = blockIdx.x;
    const int v0 = vt * VT;

#pragma unroll
    for (int k = 0; k < 16; k++) {
        int idx = k * 256 + t;                   // 0..4095
        int v = idx >> 5, h = idx & 31;
        const float4* p = (const float4*)(vocab_emb + (size_t)(v0 + v) * N_EMBD + h * HEAD_DIM);
        float s = 0.f;
#pragma unroll
        for (int i = 0; i < 8; i++) { float4 f = p[i]; s += (f.x + f.y) + (f.z + f.w); }
        T[v][h] = __float2half_rn(s);
    }
    __syncthreads();

    // Skv: [v][h] rows of 64B data, contiguous u32 stores
    char* gk = g_Skv + (size_t)vt * SKV_TILE;
#pragma unroll
    for (int k = 0; k < 8; k++) {
        int idx = k * 256 + t;                   // 0..2047: v=idx>>4, c=idx&15
        int v = idx >> 4, c = idx & 15;
        uint32_t val = *(const uint32_t*)&T[v][2 * c];
        *(uint32_t*)(gk + v * SKV_ROW + c * 4) = val;
    }
    // Shv: [h][v] rows of 256B data (transpose read from smem)
    char* gh = g_Shv + (size_t)vt * SHV_TILE;
#pragma unroll
    for (int k = 0; k < 8; k++) {
        int idx = k * 256 + t;                   // 0..2047: h=idx>>6, c=idx&63
        int h = idx >> 6, c = idx & 63;
        uint16_t a = *(const uint16_t*)&T[2 * c][h];
        uint16_t b = *(const uint16_t*)&T[2 * c + 1][h];
        uint32_t val = ((uint32_t)b << 16) | (uint32_t)a;
        *(uint32_t*)(gh + h * SHV_ROW + c * 4) = val;
    }
    // rows 32..39: row 32 = ones (Z column), rows 33..39 = zeros
#pragma unroll
    for (int idx = t; idx < 512; idx += 256) {
        int h = 32 + (idx >> 6), c = idx & 63;
        uint32_t val = (h == 32) ? 0x3C003C00u : 0u;
        *(uint32_t*)(gh + h * SHV_ROW + c * 4) = val;
    }
}

// ---------------- kernel 2: Q = FFN(x) -> f16 ----------------------------------
__global__ void __launch_bounds__(256)
qbuild_kernel(const float* __restrict__ x,
              const float* __restrict__ W, const float* __restrict__ b) {
    __shared__ float sW[32 * 33];
    __shared__ float sx[8][32];
    const int t = threadIdx.x;
    const int row0 = blockIdx.x * 8;
#pragma unroll
    for (int k = 0; k < 4; k++) {
        int i = k * 256 + t;
        sW[(i >> 5) * 33 + (i & 31)] = W[i];
    }
    const int rl = t >> 5, d = t & 31;
    const int row = row0 + rl;
    sx[rl][d] = x[(size_t)row * 32 + d];
    __syncthreads();

    float s = b[d];
    const float* wr = sW + d * 33;
#pragma unroll
    for (int h = 0; h < 32; h++) s = fmaf(sx[rl][h], wr[h], s);
    g_Qh[row * 32 + d] = __float2half_rn(s);
}

// ---------------- flash kernel: warp-MMA fp16, fused exp, Z-in-MMA -------------
// grid = MTILES*NSPLIT.  blockDim = 256 (8 warps, M=16 rows each).
__global__ void __launch_bounds__(256, 2)
flash_kernel(const float* __restrict__ temps) {
    __shared__ __align__(16) char skv[2][SKV_TILE];
    __shared__ __align__(16) char shv[2][SHV_TILE];

    const int tid = threadIdx.x, w = tid >> 5, lane = tid & 31;
    const int gid = lane >> 2, tig = lane & 3;
    const int m = blockIdx.x & (MTILES - 1), s = blockIdx.x >> 5;
    const int rw0 = m * 128 + w * 16;                 // first global row of this warp
    const int t0 = (s * NTILES) / NSPLIT, t1 = ((s + 1) * NTILES) / NSPLIT;
    const int nT = t1 - t0;

    const uint32_t skv_b[2] = { smem_to_u32(skv[0]), smem_to_u32(skv[1]) };
    const uint32_t shv_b[2] = { smem_to_u32(shv[0]), smem_to_u32(shv[1]) };

    // ---- persistent Q fragments (A of GEMM1): m16k16, ksteps 0,1 ----
    uint32_t qf[2][4];
#pragma unroll
    for (int ks = 0; ks < 2; ks++) {
        int c0 = ks * 16 + 2 * tig;
        qf[ks][0] = *(const uint32_t*)&g_Qh[(size_t)(rw0 + gid)     * 32 + c0];
        qf[ks][1] = *(const uint32_t*)&g_Qh[(size_t)(rw0 + gid + 8) * 32 + c0];
        qf[ks][2] = *(const uint32_t*)&g_Qh[(size_t)(rw0 + gid)     * 32 + c0 + 8];
        qf[ks][3] = *(const uint32_t*)&g_Qh[(size_t)(rw0 + gid + 8) * 32 + c0 + 8];
    }

    // softmax scales for this thread's two row groups (head = row % 32)
    const int h0 = ((w & 1) * 16 + gid);
    const float s2a = LOG2E / fmaxf(temps[h0],     TEMP_MIN);
    const float s2b = LOG2E / fmaxf(temps[h0 + 8], TEMP_MIN);

    float outacc[5][4];
#pragma unroll
    for (int n2 = 0; n2 < 5; n2++)
#pragma unroll
        for (int k = 0; k < 4; k++) outacc[n2][k] = 0.f;

    // ---- cp.async tile copy helper ----
    // SKV_TILE = 640 x 16B chunks; SHV_TILE = 680 x 16B chunks.
    auto issue_tile = [&](int stg, int vt) {
        const char* gk = g_Skv + (size_t)vt * SKV_TILE;
        const char* gh = g_Shv + (size_t)vt * SHV_TILE;
        uint32_t dk = skv_b[stg], dh = shv_b[stg];
        CP_ASYNC16(dk + tid * 16,         gk + tid * 16);
        CP_ASYNC16(dk + 4096 + tid * 16,  gk + 4096 + tid * 16);
        if (tid < 128) CP_ASYNC16(dk + 8192 + tid * 16, gk + 8192 + tid * 16);
        CP_ASYNC16(dh + tid * 16,         gh + tid * 16);
        CP_ASYNC16(dh + 4096 + tid * 16,  gh + 4096 + tid * 16);
        if (tid < 168) CP_ASYNC16(dh + 8192 + tid * 16, gh + 8192 + tid * 16);
        CP_COMMIT();
    };

    issue_tile(0, t0);

    for (int i = 0; i < nT; i++) {
        const int stg = i & 1;
        __syncthreads();                       // stage (i+1)&1 fully consumed
        if (i + 1 < nT) issue_tile((i + 1) & 1, t0 + i + 1);
        if (i + 1 < nT) { CP_WAIT(1); } else { CP_WAIT(0); }
        __syncthreads();                       // stage stg visible to all

        const uint32_t kv = skv_b[stg];
        const uint32_t hv = shv_b[stg];

#pragma unroll 2
        for (int c0 = 0; c0 < VT; c0 += 16) {  // 16-vocab chunk
            // B-fragments for GEMM1: cols c0+8j+gid, both ksteps
            uint32_t bA[2][2][2];
#pragma unroll
            for (int j = 0; j < 2; j++) {
                uint32_t rbase = kv + (uint32_t)((c0 + j * 8 + gid) * SKV_ROW + tig * 4);
#pragma unroll
                for (int ks = 0; ks < 2; ks++) {
                    asm volatile("ld.shared.b32 %0, [%1];" : "=r"(bA[j][ks][0]) : "r"(rbase + ks * 32));
                    asm volatile("ld.shared.b32 %0, [%1];" : "=r"(bA[j][ks][1]) : "r"(rbase + ks * 32 + 16));
                }
            }
            // logits chunk
            float d0[4] = {0.f, 0.f, 0.f, 0.f}, d1[4] = {0.f, 0.f, 0.f, 0.f};
            mma16816h(d0, qf[0], bA[0][0], d0);
            mma16816h(d0, qf[1], bA[0][1], d0);
            mma16816h(d1, qf[0], bA[1][0], d1);
            mma16816h(d1, qf[1], bA[1][1], d1);

            // exp2 of scaled logits, packed f16x2 -> A-fragment of GEMM2 directly
            uint32_t pa[4];
            pa[0] = ex2_f16x2(cvt_f16x2(d0[0] * s2a, d0[1] * s2a));
            pa[1] = ex2_f16x2(cvt_f16x2(d0[2] * s2b, d0[3] * s2b));
            pa[2] = ex2_f16x2(cvt_f16x2(d1[0] * s2a, d1[1] * s2a));
            pa[3] = ex2_f16x2(cvt_f16x2(d1[2] * s2b, d1[3] * s2b));

            // GEMM2: out[16,40] += P_chunk @ S^T_chunk  (cols 32..39: Z ones-column)
#pragma unroll
            for (int n2 = 0; n2 < 5; n2++) {
                uint32_t rbase = hv + (uint32_t)((n2 * 8 + gid) * SHV_ROW + (c0 + 2 * tig) * 2);
                uint32_t bB[2];
                asm volatile("ld.shared.b32 %0, [%1];" : "=r"(bB[0]) : "r"(rbase));
                asm volatile("ld.shared.b32 %0, [%1];" : "=r"(bB[1]) : "r"(rbase + 16));
                mma16816h(outacc[n2], pa, bB, outacc[n2]);
            }
        }
    }

    // ---- epilogue: Z comes from ones-column (col 32 -> tig==0) ----
    const int r0g = rw0 + gid, r1g = rw0 + gid + 8;
    if (tig == 0) {
        g_Zpart[s * NROWS + r0g] = outacc[4][0];
        g_Zpart[s * NROWS + r1g] = outacc[4][2];
    }
#pragma unroll
    for (int n2 = 0; n2 < 4; n2++) {
        int col = n2 * 8 + 2 * tig;
        *(float2*)&g_Opart[((size_t)s * NROWS + r0g) * 32 + col] =
            make_float2(outacc[n2][0], outacc[n2][1]);
        *(float2*)&g_Opart[((size_t)s * NROWS + r1g) * 32 + col] =
            make_float2(outacc[n2][2], outacc[n2][3]);
    }
}

// ---------------- merge partials + gate -> Q2 ----------------------------------
__global__ void __launch_bounds__(256)
merge_gate_kernel(const float* __restrict__ x,
                  const float* __restrict__ W_ref, const float* __restrict__ b_ref,
                  const float* __restrict__ W_gate, const float* __restrict__ b_gate) {
    __shared__ float sWr[32 * 33], sWg[32 * 33];
    __shared__ float sx[8][32];
    const int t = threadIdx.x;
    const int row0 = blockIdx.x * 8;
#pragma unroll
    for (int k = 0; k < 4; k++) {
        int i = k * 256 + t;
        int di = (i >> 5) * 33 + (i & 31);
        sWr[di] = W_ref[i];
        sWg[di] = W_gate[i];
    }
    const int rl = t >> 5, d = t & 31;
    const int row = row0 + rl;
    sx[rl][d] = x[(size_t)row * 32 + d];

    float O = 0.f, Z = 0.f;
#pragma unroll
    for (int s = 0; s < NSPLIT; s++) {
        O += g_Opart[((size_t)s * NROWS + row) * 32 + d];
        Z += g_Zpart[s * NROWS + row];
    }
    float vout = O / Z;
    __syncthreads();

    float sr = b_ref[d], sg = b_gate[d];
    const float* wr = sWr + d * 33;
    const float* wg = sWg + d * 33;
#pragma unroll
    for (int h = 0; h < 32; h++) {
        float xv = sx[rl][h];
        sr = fmaf(xv, wr[h], sr);
        sg = fmaf(xv, wg[h], sg);
    }
    float refv = tanhf(sr);
    float g = 1.0f / (1.0f + __expf(-sg));
    float q2 = vout * (1.0f - g) + refv * g;
    g_Qh[row * 32 + d] = __float2half_rn(q2);
}

// ---------------- final merge -> out (vectorized) ------------------------------
__global__ void final_kernel(float* __restrict__ out) {
    int gid = blockIdx.x * blockDim.x + threadIdx.x;      // NROWS*8
    if (gid >= NROWS * 8) return;
    int row = gid >> 3, c4 = (gid & 7) * 4;
    float4 O = make_float4(0.f, 0.f, 0.f, 0.f);
    float Z = 0.f;
#pragma unroll
    for (int s = 0; s < NSPLIT; s++) {
        float4 o = *(const float4*)&g_Opart[((size_t)s * NROWS + row) * 32 + c4];
        O.x += o.x; O.y += o.y; O.z += o.z; O.w += o.w;
        Z += g_Zpart[s * NROWS + row];
    }
    float iz = 1.0f / Z;
    *(float4*)&out[(size_t)row * 32 + c4] =
        make_float4(O.x * iz, O.y * iz, O.z * iz, O.w * iz);
}

// ---------------- launch -------------------------------------------------------
extern "C" void kernel_launch(void* const* d_in, const int* in_sizes, int n_in,
                              void* d_out, int out_size) {
    const float* x         = (const float*)d_in[0];
    const float* vocab_emb = (const float*)d_in[1];
    const float* W_ffn     = (const float*)d_in[2];
    const float* b_ffn     = (const float*)d_in[3];
    const float* temps     = (const float*)d_in[4];
    const float* W_ref     = (const float*)d_in[5];
    const float* b_ref     = (const float*)d_in[6];
    const float* W_gate    = (const float*)d_in[7];
    const float* b_gate    = (const float*)d_in[8];
    float* out = (float*)d_out;

    build_S_tiles<<<NTILES, 256>>>(vocab_emb);
    qbuild_kernel<<<NROWS / 8, 256>>>(x, W_ffn, b_ffn);
    flash_kernel<<<MTILES * NSPLIT, 256>>>(temps);
    merge_gate_kernel<<<NROWS / 8, 256>>>(x, W_ref, b_ref, W_gate, b_gate);
    flash_kernel<<<MTILES * NSPLIT, 256>>>(temps);
    final_kernel<<<(NROWS * 8 + 255) / 256, 256>>>(out);
}

// round 7
// speedup vs baseline: 10.3473x; 1.1026x over previous
#include <cuda_runtime.h>
#include <cuda_fp16.h>
#include <cstdint>

#define N_HEAD   32
#define HEAD_DIM 32
#define N_EMBD   1024
#define VOCAB    32000
#define NTOK     128
#define NROWS    4096            // NTOK * N_HEAD
#define TEMP_MIN 0.1f
#define LOG2E    1.4426950408889634f

#define VT       128             // vocab columns per tile
#define NTILES   250             // 32000 / 128
#define NSPLIT   9
#define MTILES   32              // 4096 / 128

// padded tile layouts (conflict-free LDS for B-fragments)
#define SKV_ROW   80             // 32 f16 (64B) + 16B pad
#define SKV_TILE  (VT * SKV_ROW)          // 10240 B
#define SHV_ROW   272            // 128 f16 (256B) + 16B pad
#define SHV_NROW  40             // 32 data rows + ones row (32) + 7 zero rows
#define SHV_TILE  (SHV_NROW * SHV_ROW)    // 10880 B

// ---------------- global scratch ----------------------------------------------
__device__ __align__(256) char g_Skv[NTILES * SKV_TILE];   // [tile][v][ch] f16 padded
__device__ __align__(256) char g_Shv[NTILES * SHV_TILE];   // [tile][ch][v] f16 padded
__device__ __align__(256) __half g_Qh[NROWS * 32];         // pre-scaled by log2e/temp
__device__ __align__(256) float g_Opart[NSPLIT * NROWS * 32];
__device__ __align__(256) float g_Zpart[NSPLIT * NROWS];

// ---------------- helpers ------------------------------------------------------
__device__ __forceinline__ uint32_t smem_to_u32(const void* p) {
    uint32_t a;
    asm("{ .reg .u64 t; cvta.to.shared.u64 t, %1; cvt.u32.u64 %0, t; }" : "=r"(a) : "l"(p));
    return a;
}
#define CP_ASYNC16(dst_u32, src_ptr) \
    asm volatile("cp.async.cg.shared.global [%0], [%1], 16;" \
                 :: "r"(dst_u32), "l"(src_ptr) : "memory")
#define CP_COMMIT()  asm volatile("cp.async.commit_group;" ::: "memory")
#define CP_WAIT(n)   asm volatile("cp.async.wait_group %0;" :: "n"(n) : "memory")

// pack two f32 into f16x2 (second value -> high half), then exp2 both
__device__ __forceinline__ uint32_t cvt_f16x2(float lo, float hi) {
    uint32_t r;
    asm("cvt.rn.f16x2.f32 %0, %1, %2;" : "=r"(r) : "f"(hi), "f"(lo));
    return r;
}
__device__ __forceinline__ uint32_t ex2_f16x2(uint32_t x) {
    uint32_t r;
    asm("ex2.approx.f16x2 %0, %1;" : "=r"(r) : "r"(x));
    return r;
}
// D = A(16x16 f16,row) @ B(16x8 f16,col) + C   (f32 accum)
__device__ __forceinline__ void mma16816h(float* d, const uint32_t* a, const uint32_t* b,
                                          const float* c) {
    asm volatile("mma.sync.aligned.m16n8k16.row.col.f32.f16.f16.f32 "
                 "{%0,%1,%2,%3}, {%4,%5,%6,%7}, {%8,%9}, {%10,%11,%12,%13};"
                 : "=f"(d[0]), "=f"(d[1]), "=f"(d[2]), "=f"(d[3])
                 : "r"(a[0]), "r"(a[1]), "r"(a[2]), "r"(a[3]),
                   "r"(b[0]), "r"(b[1]),
                   "f"(c[0]), "f"(c[1]), "f"(c[2]), "f"(c[3]));
}

// ---------------- kernel 1: build f16 S tiles (smem transpose, coalesced) ------
__global__ void __launch_bounds__(256)
build_S_tiles(const float* __restrict__ vocab_emb) {
    __shared__ __half T[128][34];                // +2 pad
    const int t = threadIdx.x, vt = blockIdx.x;
    const int v0 = vt * VT;

#pragma unroll
    for (int k = 0; k < 16; k++) {
        int idx = k * 256 + t;                   // 0..4095
        int v = idx >> 5, h = idx & 31;
        const float4* p = (const float4*)(vocab_emb + (size_t)(v0 + v) * N_EMBD + h * HEAD_DIM);
        float s = 0.f;
#pragma unroll
        for (int i = 0; i < 8; i++) { float4 f = p[i]; s += (f.x + f.y) + (f.z + f.w); }
        T[v][h] = __float2half_rn(s);
    }
    __syncthreads();

    char* gk = g_Skv + (size_t)vt * SKV_TILE;
#pragma unroll
    for (int k = 0; k < 8; k++) {
        int idx = k * 256 + t;                   // v=idx>>4, c=idx&15
        int v = idx >> 4, c = idx & 15;
        uint32_t val = *(const uint32_t*)&T[v][2 * c];
        *(uint32_t*)(gk + v * SKV_ROW + c * 4) = val;
    }
    char* gh = g_Shv + (size_t)vt * SHV_TILE;
#pragma unroll
    for (int k = 0; k < 8; k++) {
        int idx = k * 256 + t;                   // h=idx>>6, c=idx&63
        int h = idx >> 6, c = idx & 63;
        uint16_t a = *(const uint16_t*)&T[2 * c][h];
        uint16_t b = *(const uint16_t*)&T[2 * c + 1][h];
        uint32_t val = ((uint32_t)b << 16) | (uint32_t)a;
        *(uint32_t*)(gh + h * SHV_ROW + c * 4) = val;
    }
    // rows 32..39: row 32 = ones (Z column), rows 33..39 = zeros
#pragma unroll
    for (int idx = t; idx < 512; idx += 256) {
        int h = 32 + (idx >> 6), c = idx & 63;
        uint32_t val = (h == 32) ? 0x3C003C00u : 0u;
        *(uint32_t*)(gh + h * SHV_ROW + c * 4) = val;
    }
}

// ---------------- kernel 2: Q = FFN(x) * log2e/temp -> f16 ---------------------
__global__ void __launch_bounds__(256)
qbuild_kernel(const float* __restrict__ x,
              const float* __restrict__ W, const float* __restrict__ b,
              const float* __restrict__ temps) {
    __shared__ float sW[32 * 33];
    __shared__ float sx[8][32];
    const int t = threadIdx.x;
    const int row0 = blockIdx.x * 8;
#pragma unroll
    for (int k = 0; k < 4; k++) {
        int i = k * 256 + t;
        sW[(i >> 5) * 33 + (i & 31)] = W[i];
    }
    const int rl = t >> 5, d = t & 31;
    const int row = row0 + rl;
    sx[rl][d] = x[(size_t)row * 32 + d];
    __syncthreads();

    float s = b[d];
    const float* wr = sW + d * 33;
#pragma unroll
    for (int h = 0; h < 32; h++) s = fmaf(sx[rl][h], wr[h], s);
    float s2 = LOG2E / fmaxf(temps[row & 31], TEMP_MIN);
    g_Qh[row * 32 + d] = __float2half_rn(s * s2);
}

// ---------------- flash kernel: 4 warps, M=32/warp, pre-scaled Q ---------------
// grid = MTILES*NSPLIT.  blockDim = 128 (4 warps).
__global__ void __launch_bounds__(128, 4)
flash_kernel() {
    __shared__ __align__(16) char skv[2][SKV_TILE];
    __shared__ __align__(16) char shv[2][SHV_TILE];

    const int tid = threadIdx.x, w = tid >> 5, lane = tid & 31;
    const int gid = lane >> 2, tig = lane & 3;
    const int m = blockIdx.x & (MTILES - 1), s = blockIdx.x >> 5;
    const int rw0 = m * 128 + w * 32;                 // first of 32 rows for this warp
    const int t0 = (s * NTILES) / NSPLIT, t1 = ((s + 1) * NTILES) / NSPLIT;
    const int nT = t1 - t0;

    const uint32_t skv_b[2] = { smem_to_u32(skv[0]), smem_to_u32(skv[1]) };
    const uint32_t shv_b[2] = { smem_to_u32(shv[0]), smem_to_u32(shv[1]) };

    // ---- persistent Q fragments: 2 M-frags (rows rw0+16f), 2 ksteps ----
    uint32_t qf[2][2][4];
#pragma unroll
    for (int f = 0; f < 2; f++)
#pragma unroll
    for (int ks = 0; ks < 2; ks++) {
        int c0 = ks * 16 + 2 * tig;
        int rb = rw0 + 16 * f;
        qf[f][ks][0] = *(const uint32_t*)&g_Qh[(size_t)(rb + gid)     * 32 + c0];
        qf[f][ks][1] = *(const uint32_t*)&g_Qh[(size_t)(rb + gid + 8) * 32 + c0];
        qf[f][ks][2] = *(const uint32_t*)&g_Qh[(size_t)(rb + gid)     * 32 + c0 + 8];
        qf[f][ks][3] = *(const uint32_t*)&g_Qh[(size_t)(rb + gid + 8) * 32 + c0 + 8];
    }

    float outacc[2][5][4];
#pragma unroll
    for (int f = 0; f < 2; f++)
#pragma unroll
    for (int n2 = 0; n2 < 5; n2++)
#pragma unroll
        for (int k = 0; k < 4; k++) outacc[f][n2][k] = 0.f;

    // ---- cp.async tile copy (128 threads): SKV 640 chunks, SHV 680 chunks ----
    auto issue_tile = [&](int stg, int vt) {
        const char* gk = g_Skv + (size_t)vt * SKV_TILE;
        const char* gh = g_Shv + (size_t)vt * SHV_TILE;
        uint32_t dk = skv_b[stg], dh = shv_b[stg];
#pragma unroll
        for (int c = 0; c < 5; c++)
            CP_ASYNC16(dk + c * 2048 + tid * 16, gk + c * 2048 + tid * 16);
#pragma unroll
        for (int c = 0; c < 5; c++)
            CP_ASYNC16(dh + c * 2048 + tid * 16, gh + c * 2048 + tid * 16);
        if (tid < 40) CP_ASYNC16(dh + 10240 + tid * 16, gh + 10240 + tid * 16);
        CP_COMMIT();
    };

    issue_tile(0, t0);

    for (int i = 0; i < nT; i++) {
        const int stg = i & 1;
        __syncthreads();                       // stage (i+1)&1 fully consumed
        if (i + 1 < nT) issue_tile((i + 1) & 1, t0 + i + 1);
        if (i + 1 < nT) { CP_WAIT(1); } else { CP_WAIT(0); }
        __syncthreads();                       // stage stg visible

        const uint32_t kv = skv_b[stg];
        const uint32_t hv = shv_b[stg];

#pragma unroll 2
        for (int c0 = 0; c0 < VT; c0 += 16) {  // 16-vocab chunk
            // B-fragments for GEMM1 (shared across both M-frags)
            uint32_t bA[2][2][2];
#pragma unroll
            for (int j = 0; j < 2; j++) {
                uint32_t rbase = kv + (uint32_t)((c0 + j * 8 + gid) * SKV_ROW + tig * 4);
#pragma unroll
                for (int ks = 0; ks < 2; ks++) {
                    asm volatile("ld.shared.b32 %0, [%1];" : "=r"(bA[j][ks][0]) : "r"(rbase + ks * 32));
                    asm volatile("ld.shared.b32 %0, [%1];" : "=r"(bA[j][ks][1]) : "r"(rbase + ks * 32 + 16));
                }
            }
            // GEMM1 + exp2 -> A-fragments of GEMM2, per M-frag
            uint32_t pa[2][4];
#pragma unroll
            for (int f = 0; f < 2; f++) {
                float d0[4] = {0.f, 0.f, 0.f, 0.f}, d1[4] = {0.f, 0.f, 0.f, 0.f};
                mma16816h(d0, qf[f][0], bA[0][0], d0);
                mma16816h(d0, qf[f][1], bA[0][1], d0);
                mma16816h(d1, qf[f][0], bA[1][0], d1);
                mma16816h(d1, qf[f][1], bA[1][1], d1);
                pa[f][0] = ex2_f16x2(cvt_f16x2(d0[0], d0[1]));
                pa[f][1] = ex2_f16x2(cvt_f16x2(d0[2], d0[3]));
                pa[f][2] = ex2_f16x2(cvt_f16x2(d1[0], d1[1]));
                pa[f][3] = ex2_f16x2(cvt_f16x2(d1[2], d1[3]));
            }
            // GEMM2: out[32,40] += P @ S^T (col 32 block = Z ones-column)
#pragma unroll
            for (int n2 = 0; n2 < 5; n2++) {
                uint32_t rbase = hv + (uint32_t)((n2 * 8 + gid) * SHV_ROW + (c0 + 2 * tig) * 2);
                uint32_t bB[2];
                asm volatile("ld.shared.b32 %0, [%1];" : "=r"(bB[0]) : "r"(rbase));
                asm volatile("ld.shared.b32 %0, [%1];" : "=r"(bB[1]) : "r"(rbase + 16));
                mma16816h(outacc[0][n2], pa[0], bB, outacc[0][n2]);
                mma16816h(outacc[1][n2], pa[1], bB, outacc[1][n2]);
            }
        }
    }

    // ---- epilogue: Z from ones-column (col 32 -> tig==0) ----
#pragma unroll
    for (int f = 0; f < 2; f++) {
        const int r0g = rw0 + 16 * f + gid, r1g = r0g + 8;
        if (tig == 0) {
            g_Zpart[s * NROWS + r0g] = outacc[f][4][0];
            g_Zpart[s * NROWS + r1g] = outacc[f][4][2];
        }
#pragma unroll
        for (int n2 = 0; n2 < 4; n2++) {
            int col = n2 * 8 + 2 * tig;
            *(float2*)&g_Opart[((size_t)s * NROWS + r0g) * 32 + col] =
                make_float2(outacc[f][n2][0], outacc[f][n2][1]);
            *(float2*)&g_Opart[((size_t)s * NROWS + r1g) * 32 + col] =
                make_float2(outacc[f][n2][2], outacc[f][n2][3]);
        }
    }
}

// ---------------- merge partials + gate -> Q2 (pre-scaled) ---------------------
__global__ void __launch_bounds__(256)
merge_gate_kernel(const float* __restrict__ x,
                  const float* __restrict__ W_ref, const float* __restrict__ b_ref,
                  const float* __restrict__ W_gate, const float* __restrict__ b_gate,
                  const float* __restrict__ temps) {
    __shared__ float sWr[32 * 33], sWg[32 * 33];
    __shared__ float sx[8][32];
    const int t = threadIdx.x;
    const int row0 = blockIdx.x * 8;
#pragma unroll
    for (int k = 0; k < 4; k++) {
        int i = k * 256 + t;
        int di = (i >> 5) * 33 + (i & 31);
        sWr[di] = W_ref[i];
        sWg[di] = W_gate[i];
    }
    const int rl = t >> 5, d = t & 31;
    const int row = row0 + rl;
    sx[rl][d] = x[(size_t)row * 32 + d];

    float O = 0.f, Z = 0.f;
#pragma unroll
    for (int s = 0; s < NSPLIT; s++) {
        O += g_Opart[((size_t)s * NROWS + row) * 32 + d];
        Z += g_Zpart[s * NROWS + row];
    }
    float vout = O / Z;
    __syncthreads();

    float sr = b_ref[d], sg = b_gate[d];
    const float* wr = sWr + d * 33;
    const float* wg = sWg + d * 33;
#pragma unroll
    for (int h = 0; h < 32; h++) {
        float xv = sx[rl][h];
        sr = fmaf(xv, wr[h], sr);
        sg = fmaf(xv, wg[h], sg);
    }
    float refv = tanhf(sr);
    float g = 1.0f / (1.0f + __expf(-sg));
    float q2 = vout * (1.0f - g) + refv * g;
    float s2 = LOG2E / fmaxf(temps[row & 31], TEMP_MIN);
    g_Qh[row * 32 + d] = __float2half_rn(q2 * s2);
}

// ---------------- final merge -> out (vectorized) ------------------------------
__global__ void final_kernel(float* __restrict__ out) {
    int gid = blockIdx.x * blockDim.x + threadIdx.x;      // NROWS*8
    if (gid >= NROWS * 8) return;
    int row = gid >> 3, c4 = (gid & 7) * 4;
    float4 O = make_float4(0.f, 0.f, 0.f, 0.f);
    float Z = 0.f;
#pragma unroll
    for (int s = 0; s < NSPLIT; s++) {
        float4 o = *(const float4*)&g_Opart[((size_t)s * NROWS + row) * 32 + c4];
        O.x += o.x; O.y += o.y; O.z += o.z; O.w += o.w;
        Z += g_Zpart[s * NROWS + row];
    }
    float iz = 1.0f / Z;
    *(float4*)&out[(size_t)row * 32 + c4] =
        make_float4(O.x * iz, O.y * iz, O.z * iz, O.w * iz);
}

// ---------------- launch -------------------------------------------------------
extern "C" void kernel_launch(void* const* d_in, const int* in_sizes, int n_in,
                              void* d_out, int out_size) {
    const float* x         = (const float*)d_in[0];
    const float* vocab_emb = (const float*)d_in[1];
    const float* W_ffn     = (const float*)d_in[2];
    const float* b_ffn     = (const float*)d_in[3];
    const float* temps     = (const float*)d_in[4];
    const float* W_ref     = (const float*)d_in[5];
    const float* b_ref     = (const float*)d_in[6];
    const float* W_gate    = (const float*)d_in[7];
    const float* b_gate    = (const float*)d_in[8];
    float* out = (float*)d_out;

    build_S_tiles<<<NTILES, 256>>>(vocab_emb);
    qbuild_kernel<<<NROWS / 8, 256>>>(x, W_ffn, b_ffn, temps);
    flash_kernel<<<MTILES * NSPLIT, 128>>>();
    merge_gate_kernel<<<NROWS / 8, 256>>>(x, W_ref, b_ref, W_gate, b_gate, temps);
    flash_kernel<<<MTILES * NSPLIT, 128>>>();
    final_kernel<<<(NROWS * 8 + 255) / 256, 256>>>(out);
}

// round 8
// speedup vs baseline: 10.9034x; 1.0537x over previous
#include <cuda_runtime.h>
#include <cuda_fp16.h>
#include <cstdint>

#define N_HEAD   32
#define HEAD_DIM 32
#define N_EMBD   1024
#define VOCAB    32000
#define NTOK     128
#define NROWS    4096            // NTOK * N_HEAD
#define TEMP_MIN 0.1f
#define LOG2E    1.4426950408889634f

#define VT       128             // vocab columns per tile
#define NTILES   250             // 32000 / 128
#define NSPLIT   18
#define MTILES   32              // 4096 / 128

// padded tile layouts (LDSM-conflict-free strides)
#define SKV_ROW   80             // 32 f16 (64B) + 16B pad
#define SKV_TILE  (VT * SKV_ROW)          // 10240 B
#define SHV_ROW   272            // 128 f16 (256B) + 16B pad
#define SHV_NROW  40             // 32 data rows + ones row (32) + 7 zero rows
#define SHV_TILE  (SHV_NROW * SHV_ROW)    // 10880 B

// ---------------- global scratch ----------------------------------------------
__device__ __align__(256) char g_Skv[NTILES * SKV_TILE];   // [tile][v][ch] f16 padded
__device__ __align__(256) char g_Shv[NTILES * SHV_TILE];   // [tile][ch][v] f16 padded
__device__ __align__(256) __half g_Qh[NROWS * 32];         // pre-scaled by log2e/temp
__device__ __align__(256) float g_Opart[NSPLIT * NROWS * 32];
__device__ __align__(256) float g_Zpart[NSPLIT * NROWS];

// ---------------- helpers ------------------------------------------------------
__device__ __forceinline__ uint32_t smem_to_u32(const void* p) {
    uint32_t a;
    asm("{ .reg .u64 t; cvta.to.shared.u64 t, %1; cvt.u32.u64 %0, t; }" : "=r"(a) : "l"(p));
    return a;
}
#define CP_ASYNC16(dst_u32, src_ptr) \
    asm volatile("cp.async.cg.shared.global [%0], [%1], 16;" \
                 :: "r"(dst_u32), "l"(src_ptr) : "memory")
#define CP_COMMIT()  asm volatile("cp.async.commit_group;" ::: "memory")
#define CP_WAIT(n)   asm volatile("cp.async.wait_group %0;" :: "n"(n) : "memory")

#define LDSM4(r0, r1, r2, r3, addr) \
    asm volatile("ldmatrix.sync.aligned.m8n8.x4.shared.b16 {%0,%1,%2,%3}, [%4];" \
                 : "=r"(r0), "=r"(r1), "=r"(r2), "=r"(r3) : "r"(addr))
#define LDSM2(r0, r1, addr) \
    asm volatile("ldmatrix.sync.aligned.m8n8.x2.shared.b16 {%0,%1}, [%2];" \
                 : "=r"(r0), "=r"(r1) : "r"(addr))

// pack two f32 into f16x2 (second value -> high half), then exp2 both
__device__ __forceinline__ uint32_t cvt_f16x2(float lo, float hi) {
    uint32_t r;
    asm("cvt.rn.f16x2.f32 %0, %1, %2;" : "=r"(r) : "f"(hi), "f"(lo));
    return r;
}
__device__ __forceinline__ uint32_t ex2_f16x2(uint32_t x) {
    uint32_t r;
    asm("ex2.approx.f16x2 %0, %1;" : "=r"(r) : "r"(x));
    return r;
}
// D = A(16x16 f16,row) @ B(16x8 f16,col) + C   (f32 accum)
__device__ __forceinline__ void mma16816h(float* d, const uint32_t* a, const uint32_t* b0,
                                          const uint32_t* b1, const float* c) {
    asm volatile("mma.sync.aligned.m16n8k16.row.col.f32.f16.f16.f32 "
                 "{%0,%1,%2,%3}, {%4,%5,%6,%7}, {%8,%9}, {%10,%11,%12,%13};"
                 : "=f"(d[0]), "=f"(d[1]), "=f"(d[2]), "=f"(d[3])
                 : "r"(a[0]), "r"(a[1]), "r"(a[2]), "r"(a[3]),
                   "r"(*b0), "r"(*b1),
                   "f"(c[0]), "f"(c[1]), "f"(c[2]), "f"(c[3]));
}

// ---------------- kernel 1: build f16 S tiles (smem transpose, coalesced) ------
__global__ void __launch_bounds__(256)
build_S_tiles(const float* __restrict__ vocab_emb) {
    __shared__ __half T[128][34];                // +2 pad
    const int t = threadIdx.x, vt = blockIdx.x;
    const int v0 = vt * VT;

#pragma unroll
    for (int k = 0; k < 16; k++) {
        int idx = k * 256 + t;                   // 0..4095
        int v = idx >> 5, h = idx & 31;
        const float4* p = (const float4*)(vocab_emb + (size_t)(v0 + v) * N_EMBD + h * HEAD_DIM);
        float s = 0.f;
#pragma unroll
        for (int i = 0; i < 8; i++) { float4 f = p[i]; s += (f.x + f.y) + (f.z + f.w); }
        T[v][h] = __float2half_rn(s);
    }
    __syncthreads();

    char* gk = g_Skv + (size_t)vt * SKV_TILE;
#pragma unroll
    for (int k = 0; k < 8; k++) {
        int idx = k * 256 + t;                   // v=idx>>4, c=idx&15
        int v = idx >> 4, c = idx & 15;
        uint32_t val = *(const uint32_t*)&T[v][2 * c];
        *(uint32_t*)(gk + v * SKV_ROW + c * 4) = val;
    }
    char* gh = g_Shv + (size_t)vt * SHV_TILE;
#pragma unroll
    for (int k = 0; k < 8; k++) {
        int idx = k * 256 + t;                   // h=idx>>6, c=idx&63
        int h = idx >> 6, c = idx & 63;
        uint16_t a = *(const uint16_t*)&T[2 * c][h];
        uint16_t b = *(const uint16_t*)&T[2 * c + 1][h];
        uint32_t val = ((uint32_t)b << 16) | (uint32_t)a;
        *(uint32_t*)(gh + h * SHV_ROW + c * 4) = val;
    }
    // rows 32..39: row 32 = ones (Z column), rows 33..39 = zeros
#pragma unroll
    for (int idx = t; idx < 512; idx += 256) {
        int h = 32 + (idx >> 6), c = idx & 63;
        uint32_t val = (h == 32) ? 0x3C003C00u : 0u;
        *(uint32_t*)(gh + h * SHV_ROW + c * 4) = val;
    }
}

// ---------------- kernel 2: Q = FFN(x) * log2e/temp -> f16 ---------------------
__global__ void __launch_bounds__(256)
qbuild_kernel(const float* __restrict__ x,
              const float* __restrict__ W, const float* __restrict__ b,
              const float* __restrict__ temps) {
    __shared__ float sW[32 * 33];
    __shared__ float sx[8][32];
    const int t = threadIdx.x;
    const int row0 = blockIdx.x * 8;
#pragma unroll
    for (int k = 0; k < 4; k++) {
        int i = k * 256 + t;
        sW[(i >> 5) * 33 + (i & 31)] = W[i];
    }
    const int rl = t >> 5, d = t & 31;
    const int row = row0 + rl;
    sx[rl][d] = x[(size_t)row * 32 + d];
    __syncthreads();

    float s = b[d];
    const float* wr = sW + d * 33;
#pragma unroll
    for (int h = 0; h < 32; h++) s = fmaf(sx[rl][h], wr[h], s);
    float s2 = LOG2E / fmaxf(temps[row & 31], TEMP_MIN);
    g_Qh[row * 32 + d] = __float2half_rn(s * s2);
}

// ---------------- flash kernel: 4 warps, M=32/warp, ldmatrix B-loads -----------
// grid = MTILES*NSPLIT.  blockDim = 128 (4 warps).
__global__ void __launch_bounds__(128, 4)
flash_kernel() {
    __shared__ __align__(16) char skv[2][SKV_TILE];
    __shared__ __align__(16) char shv[2][SHV_TILE];

    const int tid = threadIdx.x, w = tid >> 5, lane = tid & 31;
    const int gid = lane >> 2, tig = lane & 3;
    const int lane7 = lane & 7, laneg = lane >> 3;     // ldmatrix row / tile select
    const int m = blockIdx.x & (MTILES - 1), s = blockIdx.x >> 5;
    const int rw0 = m * 128 + w * 32;                  // first of 32 rows for this warp
    const int t0 = (s * NTILES) / NSPLIT, t1 = ((s + 1) * NTILES) / NSPLIT;
    const int nT = t1 - t0;

    const uint32_t skv_b[2] = { smem_to_u32(skv[0]), smem_to_u32(skv[1]) };
    const uint32_t shv_b[2] = { smem_to_u32(shv[0]), smem_to_u32(shv[1]) };

    // ldmatrix per-lane offsets (relative to stage base):
    // GEMM1 B (Skv): tile(j): rows v=c0+8j+lane7, ch-block = laneg -> +16B*laneg
    const uint32_t aA_off = (uint32_t)(lane7 * SKV_ROW + laneg * 16);
    // GEMM2 B (Shv): LDSM1 tiles (n2=laneg>>1, khalf=laneg&1)
    const uint32_t bB_off = (uint32_t)((((laneg >> 1) * 8) + lane7) * SHV_ROW + (laneg & 1) * 16);
    // LDSM3 (x2): lanes 0..15 -> n2=4, khalf=(lane&15)>>3
    const uint32_t bZ_off = (uint32_t)((32 + (lane & 7)) * SHV_ROW + ((lane & 15) >> 3) * 16);

    // ---- persistent Q fragments: 2 M-frags (rows rw0+16f), 2 ksteps ----
    uint32_t qf[2][2][4];
#pragma unroll
    for (int f = 0; f < 2; f++)
#pragma unroll
    for (int ks = 0; ks < 2; ks++) {
        int c0 = ks * 16 + 2 * tig;
        int rb = rw0 + 16 * f;
        qf[f][ks][0] = *(const uint32_t*)&g_Qh[(size_t)(rb + gid)     * 32 + c0];
        qf[f][ks][1] = *(const uint32_t*)&g_Qh[(size_t)(rb + gid + 8) * 32 + c0];
        qf[f][ks][2] = *(const uint32_t*)&g_Qh[(size_t)(rb + gid)     * 32 + c0 + 8];
        qf[f][ks][3] = *(const uint32_t*)&g_Qh[(size_t)(rb + gid + 8) * 32 + c0 + 8];
    }

    float outacc[2][5][4];
#pragma unroll
    for (int f = 0; f < 2; f++)
#pragma unroll
    for (int n2 = 0; n2 < 5; n2++)
#pragma unroll
        for (int k = 0; k < 4; k++) outacc[f][n2][k] = 0.f;

    // ---- cp.async tile copy (128 threads) ----
    auto issue_tile = [&](int stg, int vt) {
        const char* gk = g_Skv + (size_t)vt * SKV_TILE;
        const char* gh = g_Shv + (size_t)vt * SHV_TILE;
        uint32_t dk = skv_b[stg], dh = shv_b[stg];
#pragma unroll
        for (int c = 0; c < 5; c++)
            CP_ASYNC16(dk + c * 2048 + tid * 16, gk + c * 2048 + tid * 16);
#pragma unroll
        for (int c = 0; c < 5; c++)
            CP_ASYNC16(dh + c * 2048 + tid * 16, gh + c * 2048 + tid * 16);
        if (tid < 40) CP_ASYNC16(dh + 10240 + tid * 16, gh + 10240 + tid * 16);
        CP_COMMIT();
    };

    issue_tile(0, t0);

    for (int i = 0; i < nT; i++) {
        const int stg = i & 1;
        __syncthreads();
        if (i + 1 < nT) issue_tile((i + 1) & 1, t0 + i + 1);
        if (i + 1 < nT) { CP_WAIT(1); } else { CP_WAIT(0); }
        __syncthreads();

        const uint32_t kv = skv_b[stg] + aA_off;
        const uint32_t hvB = shv_b[stg] + bB_off;
        const uint32_t hvZ = shv_b[stg] + bZ_off;

#pragma unroll 2
        for (int c0 = 0; c0 < VT; c0 += 16) {  // 16-vocab chunk
            // GEMM1 B-fragments via ldmatrix: tile j covers v=c0+8j.., 4 ch-blocks
            uint32_t bA0[4], bA1[4];
            LDSM4(bA0[0], bA0[1], bA0[2], bA0[3], kv + (uint32_t)(c0 * SKV_ROW));
            LDSM4(bA1[0], bA1[1], bA1[2], bA1[3], kv + (uint32_t)((c0 + 8) * SKV_ROW));

            // GEMM1 + exp2 -> A-fragments of GEMM2, per M-frag
            uint32_t pa[2][4];
#pragma unroll
            for (int f = 0; f < 2; f++) {
                float d0[4] = {0.f, 0.f, 0.f, 0.f}, d1[4] = {0.f, 0.f, 0.f, 0.f};
                mma16816h(d0, qf[f][0], &bA0[0], &bA0[1], d0);
                mma16816h(d0, qf[f][1], &bA0[2], &bA0[3], d0);
                mma16816h(d1, qf[f][0], &bA1[0], &bA1[1], d1);
                mma16816h(d1, qf[f][1], &bA1[2], &bA1[3], d1);
                pa[f][0] = ex2_f16x2(cvt_f16x2(d0[0], d0[1]));
                pa[f][1] = ex2_f16x2(cvt_f16x2(d0[2], d0[3]));
                pa[f][2] = ex2_f16x2(cvt_f16x2(d1[0], d1[1]));
                pa[f][3] = ex2_f16x2(cvt_f16x2(d1[2], d1[3]));
            }

            // GEMM2 B-fragments: 10 8x8 tiles via 2x LDSM4 + 1x LDSM2
            uint32_t bb[10];
            LDSM4(bb[0], bb[1], bb[2], bb[3], hvB + (uint32_t)(c0 * 2));
            LDSM4(bb[4], bb[5], bb[6], bb[7], hvB + (uint32_t)(c0 * 2) + 4352u);
            LDSM2(bb[8], bb[9], hvZ + (uint32_t)(c0 * 2));

#pragma unroll
            for (int n2 = 0; n2 < 5; n2++) {
                mma16816h(outacc[0][n2], pa[0], &bb[2 * n2], &bb[2 * n2 + 1], outacc[0][n2]);
                mma16816h(outacc[1][n2], pa[1], &bb[2 * n2], &bb[2 * n2 + 1], outacc[1][n2]);
            }
        }
    }

    // ---- epilogue: Z from ones-column (col 32 -> tig==0) ----
#pragma unroll
    for (int f = 0; f < 2; f++) {
        const int r0g = rw0 + 16 * f + gid, r1g = r0g + 8;
        if (tig == 0) {
            g_Zpart[s * NROWS + r0g] = outacc[f][4][0];
            g_Zpart[s * NROWS + r1g] = outacc[f][4][2];
        }
#pragma unroll
        for (int n2 = 0; n2 < 4; n2++) {
            int col = n2 * 8 + 2 * tig;
            *(float2*)&g_Opart[((size_t)s * NROWS + r0g) * 32 + col] =
                make_float2(outacc[f][n2][0], outacc[f][n2][1]);
            *(float2*)&g_Opart[((size_t)s * NROWS + r1g) * 32 + col] =
                make_float2(outacc[f][n2][2], outacc[f][n2][3]);
        }
    }
}

// ---------------- merge partials + gate -> Q2 (pre-scaled) ---------------------
__global__ void __launch_bounds__(256)
merge_gate_kernel(const float* __restrict__ x,
                  const float* __restrict__ W_ref, const float* __restrict__ b_ref,
                  const float* __restrict__ W_gate, const float* __restrict__ b_gate,
                  const float* __restrict__ temps) {
    __shared__ float sWr[32 * 33], sWg[32 * 33];
    __shared__ float sx[8][32];
    const int t = threadIdx.x;
    const int row0 = blockIdx.x * 8;
#pragma unroll
    for (int k = 0; k < 4; k++) {
        int i = k * 256 + t;
        int di = (i >> 5) * 33 + (i & 31);
        sWr[di] = W_ref[i];
        sWg[di] = W_gate[i];
    }
    const int rl = t >> 5, d = t & 31;
    const int row = row0 + rl;
    sx[rl][d] = x[(size_t)row * 32 + d];

    float O = 0.f, Z = 0.f;
#pragma unroll
    for (int s = 0; s < NSPLIT; s++) {
        O += g_Opart[((size_t)s * NROWS + row) * 32 + d];
        Z += g_Zpart[s * NROWS + row];
    }
    float vout = O / Z;
    __syncthreads();

    float sr = b_ref[d], sg = b_gate[d];
    const float* wr = sWr + d * 33;
    const float* wg = sWg + d * 33;
#pragma unroll
    for (int h = 0; h < 32; h++) {
        float xv = sx[rl][h];
        sr = fmaf(xv, wr[h], sr);
        sg = fmaf(xv, wg[h], sg);
    }
    float refv = tanhf(sr);
    float g = 1.0f / (1.0f + __expf(-sg));
    float q2 = vout * (1.0f - g) + refv * g;
    float s2 = LOG2E / fmaxf(temps[row & 31], TEMP_MIN);
    g_Qh[row * 32 + d] = __float2half_rn(q2 * s2);
}

// ---------------- final merge -> out (vectorized) ------------------------------
__global__ void final_kernel(float* __restrict__ out) {
    int gid = blockIdx.x * blockDim.x + threadIdx.x;      // NROWS*8
    if (gid >= NROWS * 8) return;
    int row = gid >> 3, c4 = (gid & 7) * 4;
    float4 O = make_float4(0.f, 0.f, 0.f, 0.f);
    float Z = 0.f;
#pragma unroll
    for (int s = 0; s < NSPLIT; s++) {
        float4 o = *(const float4*)&g_Opart[((size_t)s * NROWS + row) * 32 + c4];
        O.x += o.x; O.y += o.y; O.z += o.z; O.w += o.w;
        Z += g_Zpart[s * NROWS + row];
    }
    float iz = 1.0f / Z;
    *(float4*)&out[(size_t)row * 32 + c4] =
        make_float4(O.x * iz, O.y * iz, O.z * iz, O.w * iz);
}

// ---------------- launch -------------------------------------------------------
extern "C" void kernel_launch(void* const* d_in, const int* in_sizes, int n_in,
                              void* d_out, int out_size) {
    const float* x         = (const float*)d_in[0];
    const float* vocab_emb = (const float*)d_in[1];
    const float* W_ffn     = (const float*)d_in[2];
    const float* b_ffn     = (const float*)d_in[3];
    const float* temps     = (const float*)d_in[4];
    const float* W_ref     = (const float*)d_in[5];
    const float* b_ref     = (const float*)d_in[6];
    const float* W_gate    = (const float*)d_in[7];
    const float* b_gate    = (const float*)d_in[8];
    float* out = (float*)d_out;

    build_S_tiles<<<NTILES, 256>>>(vocab_emb);
    qbuild_kernel<<<NROWS / 8, 256>>>(x, W_ffn, b_ffn, temps);
    flash_kernel<<<MTILES * NSPLIT, 128>>>();
    merge_gate_kernel<<<NROWS / 8, 256>>>(x, W_ref, b_ref, W_gate, b_gate, temps);
    flash_kernel<<<MTILES * NSPLIT, 128>>>();
    final_kernel<<<(NROWS * 8 + 255) / 256, 256>>>(out);
}

// round 9
// speedup vs baseline: 11.1901x; 1.0263x over previous
#include <cuda_runtime.h>
#include <cuda_fp16.h>
#include <cstdint>

#define N_HEAD   32
#define HEAD_DIM 32
#define N_EMBD   1024
#define VOCAB    32000
#define NTOK     128
#define NROWS    4096            // NTOK * N_HEAD
#define TEMP_MIN 0.1f
#define LOG2E    1.4426950408889634f

#define VT       128             // vocab columns per tile
#define NTILES   250             // 32000 / 128
#define NSPLIT   18
#define MTILES   32              // 4096 / 128

// padded tile layouts (LDSM-conflict-free strides)
#define SKV_ROW   80             // 32 f16 (64B) + 16B pad
#define SKV_TILE  (VT * SKV_ROW)          // 10240 B
#define SHV_ROW   272            // 128 f16 (256B) + 16B pad
#define SHV_NROW  32             // 32 data rows (Z column removed)
#define SHV_TILE  (SHV_NROW * SHV_ROW)    // 8704 B

// ---------------- global scratch ----------------------------------------------
__device__ __align__(256) char g_Skv[NTILES * SKV_TILE];   // [tile][v][ch] f16 padded
__device__ __align__(256) char g_Shv[NTILES * SHV_TILE];   // [tile][ch][v] f16 padded
__device__ __align__(256) __half g_Qh[NROWS * 32];         // pre-scaled by log2e/temp
__device__ __align__(256) float g_Opart[NSPLIT * NROWS * 32];
__device__ __align__(256) float g_Zpart[NSPLIT * NROWS];

// ---------------- helpers ------------------------------------------------------
__device__ __forceinline__ uint32_t smem_to_u32(const void* p) {
    uint32_t a;
    asm("{ .reg .u64 t; cvta.to.shared.u64 t, %1; cvt.u32.u64 %0, t; }" : "=r"(a) : "l"(p));
    return a;
}
#define CP_ASYNC16(dst_u32, src_ptr) \
    asm volatile("cp.async.cg.shared.global [%0], [%1], 16;" \
                 :: "r"(dst_u32), "l"(src_ptr) : "memory")
#define CP_COMMIT()  asm volatile("cp.async.commit_group;" ::: "memory")
#define CP_WAIT(n)   asm volatile("cp.async.wait_group %0;" :: "n"(n) : "memory")

#define LDSM4(r0, r1, r2, r3, addr) \
    asm volatile("ldmatrix.sync.aligned.m8n8.x4.shared.b16 {%0,%1,%2,%3}, [%4];" \
                 : "=r"(r0), "=r"(r1), "=r"(r2), "=r"(r3) : "r"(addr))

// pack two f32 into f16x2 (second value -> high half), then exp2 both
__device__ __forceinline__ uint32_t cvt_f16x2(float lo, float hi) {
    uint32_t r;
    asm("cvt.rn.f16x2.f32 %0, %1, %2;" : "=r"(r) : "f"(hi), "f"(lo));
    return r;
}
__device__ __forceinline__ uint32_t ex2_f16x2(uint32_t x) {
    uint32_t r;
    asm("ex2.approx.f16x2 %0, %1;" : "=r"(r) : "r"(x));
    return r;
}
__device__ __forceinline__ uint32_t hadd2u(uint32_t a, uint32_t b) {
    uint32_t r;
    asm("add.f16x2 %0, %1, %2;" : "=r"(r) : "r"(a), "r"(b));
    return r;
}
// D = A(16x16 f16,row) @ B(16x8 f16,col) + C  (f32 accum) — non-volatile: let
// ptxas schedule across the f0/f1 chains.
__device__ __forceinline__ void mma16816h(float* d, const uint32_t* a, const uint32_t* b0,
                                          const uint32_t* b1, const float* c) {
    asm("mma.sync.aligned.m16n8k16.row.col.f32.f16.f16.f32 "
        "{%0,%1,%2,%3}, {%4,%5,%6,%7}, {%8,%9}, {%10,%11,%12,%13};"
        : "=f"(d[0]), "=f"(d[1]), "=f"(d[2]), "=f"(d[3])
        : "r"(a[0]), "r"(a[1]), "r"(a[2]), "r"(a[3]),
          "r"(*b0), "r"(*b1),
          "f"(c[0]), "f"(c[1]), "f"(c[2]), "f"(c[3]));
}

// ---------------- kernel 1: build f16 S tiles (smem transpose, coalesced) ------
__global__ void __launch_bounds__(256)
build_S_tiles(const float* __restrict__ vocab_emb) {
    __shared__ __half T[128][34];                // +2 pad
    const int t = threadIdx.x, vt = blockIdx.x;
    const int v0 = vt * VT;

#pragma unroll
    for (int k = 0; k < 16; k++) {
        int idx = k * 256 + t;                   // 0..4095
        int v = idx >> 5, h = idx & 31;
        const float4* p = (const float4*)(vocab_emb + (size_t)(v0 + v) * N_EMBD + h * HEAD_DIM);
        float s = 0.f;
#pragma unroll
        for (int i = 0; i < 8; i++) { float4 f = p[i]; s += (f.x + f.y) + (f.z + f.w); }
        T[v][h] = __float2half_rn(s);
    }
    __syncthreads();

    char* gk = g_Skv + (size_t)vt * SKV_TILE;
#pragma unroll
    for (int k = 0; k < 8; k++) {
        int idx = k * 256 + t;                   // v=idx>>4, c=idx&15
        int v = idx >> 4, c = idx & 15;
        uint32_t val = *(const uint32_t*)&T[v][2 * c];
        *(uint32_t*)(gk + v * SKV_ROW + c * 4) = val;
    }
    char* gh = g_Shv + (size_t)vt * SHV_TILE;
#pragma unroll
    for (int k = 0; k < 8; k++) {
        int idx = k * 256 + t;                   // h=idx>>6, c=idx&63
        int h = idx >> 6, c = idx & 63;
        uint16_t a = *(const uint16_t*)&T[2 * c][h];
        uint16_t b = *(const uint16_t*)&T[2 * c + 1][h];
        uint32_t val = ((uint32_t)b << 16) | (uint32_t)a;
        *(uint32_t*)(gh + h * SHV_ROW + c * 4) = val;
    }
}

// ---------------- kernel 2: Q = FFN(x) * log2e/temp -> f16 ---------------------
__global__ void __launch_bounds__(256)
qbuild_kernel(const float* __restrict__ x,
              const float* __restrict__ W, const float* __restrict__ b,
              const float* __restrict__ temps) {
    __shared__ float sW[32 * 33];
    __shared__ float sx[8][32];
    const int t = threadIdx.x;
    const int row0 = blockIdx.x * 8;
#pragma unroll
    for (int k = 0; k < 4; k++) {
        int i = k * 256 + t;
        sW[(i >> 5) * 33 + (i & 31)] = W[i];
    }
    const int rl = t >> 5, d = t & 31;
    const int row = row0 + rl;
    sx[rl][d] = x[(size_t)row * 32 + d];
    __syncthreads();

    float s = b[d];
    const float* wr = sW + d * 33;
#pragma unroll
    for (int h = 0; h < 32; h++) s = fmaf(sx[rl][h], wr[h], s);
    float s2 = LOG2E / fmaxf(temps[row & 31], TEMP_MIN);
    g_Qh[row * 32 + d] = __float2half_rn(s * s2);
}

// ---------------- flash kernel: 4 warps, M=32/warp, HADD2 Z path ---------------
// grid = MTILES*NSPLIT.  blockDim = 128 (4 warps).
__global__ void __launch_bounds__(128, 4)
flash_kernel() {
    __shared__ __align__(16) char skv[2][SKV_TILE];
    __shared__ __align__(16) char shv[2][SHV_TILE];

    const int tid = threadIdx.x, w = tid >> 5, lane = tid & 31;
    const int gid = lane >> 2, tig = lane & 3;
    const int lane7 = lane & 7, laneg = lane >> 3;
    const int m = blockIdx.x & (MTILES - 1), s = blockIdx.x >> 5;
    const int rw0 = m * 128 + w * 32;
    const int t0 = (s * NTILES) / NSPLIT, t1 = ((s + 1) * NTILES) / NSPLIT;
    const int nT = t1 - t0;

    const uint32_t skv_b[2] = { smem_to_u32(skv[0]), smem_to_u32(skv[1]) };
    const uint32_t shv_b[2] = { smem_to_u32(shv[0]), smem_to_u32(shv[1]) };

    // ldmatrix per-lane offsets
    const uint32_t aA_off = (uint32_t)(lane7 * SKV_ROW + laneg * 16);
    const uint32_t bB_off = (uint32_t)((((laneg >> 1) * 8) + lane7) * SHV_ROW + (laneg & 1) * 16);

    // ---- persistent Q fragments ----
    uint32_t qf[2][2][4];
#pragma unroll
    for (int f = 0; f < 2; f++)
#pragma unroll
    for (int ks = 0; ks < 2; ks++) {
        int c0 = ks * 16 + 2 * tig;
        int rb = rw0 + 16 * f;
        qf[f][ks][0] = *(const uint32_t*)&g_Qh[(size_t)(rb + gid)     * 32 + c0];
        qf[f][ks][1] = *(const uint32_t*)&g_Qh[(size_t)(rb + gid + 8) * 32 + c0];
        qf[f][ks][2] = *(const uint32_t*)&g_Qh[(size_t)(rb + gid)     * 32 + c0 + 8];
        qf[f][ks][3] = *(const uint32_t*)&g_Qh[(size_t)(rb + gid + 8) * 32 + c0 + 8];
    }

    float outacc[2][4][4];
#pragma unroll
    for (int f = 0; f < 2; f++)
#pragma unroll
    for (int n2 = 0; n2 < 4; n2++)
#pragma unroll
        for (int k = 0; k < 4; k++) outacc[f][n2][k] = 0.f;
    float zf[2][2] = {{0.f, 0.f}, {0.f, 0.f}};   // [f][rowgroup] f32 Z accumulators

    // ---- cp.async tile copy (128 threads): SKV 640 chunks, SHV 544 chunks ----
    auto issue_tile = [&](int stg, int vt) {
        const char* gk = g_Skv + (size_t)vt * SKV_TILE;
        const char* gh = g_Shv + (size_t)vt * SHV_TILE;
        uint32_t dk = skv_b[stg], dh = shv_b[stg];
#pragma unroll
        for (int c = 0; c < 5; c++)
            CP_ASYNC16(dk + c * 2048 + tid * 16, gk + c * 2048 + tid * 16);
#pragma unroll
        for (int c = 0; c < 4; c++)
            CP_ASYNC16(dh + c * 2048 + tid * 16, gh + c * 2048 + tid * 16);
        if (tid < 32) CP_ASYNC16(dh + 8192 + tid * 16, gh + 8192 + tid * 16);
        CP_COMMIT();
    };

    issue_tile(0, t0);

    for (int i = 0; i < nT; i++) {
        const int stg = i & 1;
        __syncthreads();
        if (i + 1 < nT) issue_tile((i + 1) & 1, t0 + i + 1);
        if (i + 1 < nT) { CP_WAIT(1); } else { CP_WAIT(0); }
        __syncthreads();

        const uint32_t kv = skv_b[stg] + aA_off;
        const uint32_t hvB = shv_b[stg] + bB_off;

        // per-tile f16x2 Z accumulators (16 adds max, values ~O(10) -> safe)
        uint32_t zt[2][2] = {{0u, 0u}, {0u, 0u}};

#pragma unroll 2
        for (int c0 = 0; c0 < VT; c0 += 16) {  // 16-vocab chunk
            // all ldmatrix up front: latency hides under GEMM1
            uint32_t bA0[4], bA1[4], bb[8];
            LDSM4(bA0[0], bA0[1], bA0[2], bA0[3], kv + (uint32_t)(c0 * SKV_ROW));
            LDSM4(bA1[0], bA1[1], bA1[2], bA1[3], kv + (uint32_t)((c0 + 8) * SKV_ROW));
            LDSM4(bb[0], bb[1], bb[2], bb[3], hvB + (uint32_t)(c0 * 2));
            LDSM4(bb[4], bb[5], bb[6], bb[7], hvB + (uint32_t)(c0 * 2) + 4352u);

            uint32_t pa[2][4];
#pragma unroll
            for (int f = 0; f < 2; f++) {
                float d0[4] = {0.f, 0.f, 0.f, 0.f}, d1[4] = {0.f, 0.f, 0.f, 0.f};
                mma16816h(d0, qf[f][0], &bA0[0], &bA0[1], d0);
                mma16816h(d0, qf[f][1], &bA0[2], &bA0[3], d0);
                mma16816h(d1, qf[f][0], &bA1[0], &bA1[1], d1);
                mma16816h(d1, qf[f][1], &bA1[2], &bA1[3], d1);
                pa[f][0] = ex2_f16x2(cvt_f16x2(d0[0], d0[1]));
                pa[f][1] = ex2_f16x2(cvt_f16x2(d0[2], d0[3]));
                pa[f][2] = ex2_f16x2(cvt_f16x2(d1[0], d1[1]));
                pa[f][3] = ex2_f16x2(cvt_f16x2(d1[2], d1[3]));
                // Z: rowgroup 0 = gid (pa0,pa2), rowgroup 1 = gid+8 (pa1,pa3)
                zt[f][0] = hadd2u(zt[f][0], hadd2u(pa[f][0], pa[f][2]));
                zt[f][1] = hadd2u(zt[f][1], hadd2u(pa[f][1], pa[f][3]));
            }

#pragma unroll
            for (int n2 = 0; n2 < 4; n2++) {
                mma16816h(outacc[0][n2], pa[0], &bb[2 * n2], &bb[2 * n2 + 1], outacc[0][n2]);
                mma16816h(outacc[1][n2], pa[1], &bb[2 * n2], &bb[2 * n2 + 1], outacc[1][n2]);
            }
        }

        // fold tile Z into f32
#pragma unroll
        for (int f = 0; f < 2; f++)
#pragma unroll
        for (int r = 0; r < 2; r++) {
            float2 v = __half22float2(*(__half2*)&zt[f][r]);
            zf[f][r] += v.x + v.y;
        }
    }

    // ---- epilogue: reduce Z over the 4 tig lanes, write partials ----
#pragma unroll
    for (int f = 0; f < 2; f++)
#pragma unroll
    for (int r = 0; r < 2; r++) {
        zf[f][r] += __shfl_xor_sync(0xFFFFFFFFu, zf[f][r], 1);
        zf[f][r] += __shfl_xor_sync(0xFFFFFFFFu, zf[f][r], 2);
    }

#pragma unroll
    for (int f = 0; f < 2; f++) {
        const int r0g = rw0 + 16 * f + gid, r1g = r0g + 8;
        if (tig == 0) {
            g_Zpart[s * NROWS + r0g] = zf[f][0];
            g_Zpart[s * NROWS + r1g] = zf[f][1];
        }
#pragma unroll
        for (int n2 = 0; n2 < 4; n2++) {
            int col = n2 * 8 + 2 * tig;
            *(float2*)&g_Opart[((size_t)s * NROWS + r0g) * 32 + col] =
                make_float2(outacc[f][n2][0], outacc[f][n2][1]);
            *(float2*)&g_Opart[((size_t)s * NROWS + r1g) * 32 + col] =
                make_float2(outacc[f][n2][2], outacc[f][n2][3]);
        }
    }
}

// ---------------- merge partials + gate -> Q2 (pre-scaled) ---------------------
__global__ void __launch_bounds__(256)
merge_gate_kernel(const float* __restrict__ x,
                  const float* __restrict__ W_ref, const float* __restrict__ b_ref,
                  const float* __restrict__ W_gate, const float* __restrict__ b_gate,
                  const float* __restrict__ temps) {
    __shared__ float sWr[32 * 33], sWg[32 * 33];
    __shared__ float sx[8][32];
    const int t = threadIdx.x;
    const int row0 = blockIdx.x * 8;
#pragma unroll
    for (int k = 0; k < 4; k++) {
        int i = k * 256 + t;
        int di = (i >> 5) * 33 + (i & 31);
        sWr[di] = W_ref[i];
        sWg[di] = W_gate[i];
    }
    const int rl = t >> 5, d = t & 31;
    const int row = row0 + rl;
    sx[rl][d] = x[(size_t)row * 32 + d];

    float O = 0.f, Z = 0.f;
#pragma unroll
    for (int s = 0; s < NSPLIT; s++) {
        O += g_Opart[((size_t)s * NROWS + row) * 32 + d];
        Z += g_Zpart[s * NROWS + row];
    }
    float vout = O / Z;
    __syncthreads();

    float sr = b_ref[d], sg = b_gate[d];
    const float* wr = sWr + d * 33;
    const float* wg = sWg + d * 33;
#pragma unroll
    for (int h = 0; h < 32; h++) {
        float xv = sx[rl][h];
        sr = fmaf(xv, wr[h], sr);
        sg = fmaf(xv, wg[h], sg);
    }
    float refv = tanhf(sr);
    float g = 1.0f / (1.0f + __expf(-sg));
    float q2 = vout * (1.0f - g) + refv * g;
    float s2 = LOG2E / fmaxf(temps[row & 31], TEMP_MIN);
    g_Qh[row * 32 + d] = __float2half_rn(q2 * s2);
}

// ---------------- final merge -> out (vectorized) ------------------------------
__global__ void final_kernel(float* __restrict__ out) {
    int gid = blockIdx.x * blockDim.x + threadIdx.x;      // NROWS*8
    if (gid >= NROWS * 8) return;
    int row = gid >> 3, c4 = (gid & 7) * 4;
    float4 O = make_float4(0.f, 0.f, 0.f, 0.f);
    float Z = 0.f;
#pragma unroll
    for (int s = 0; s < NSPLIT; s++) {
        float4 o = *(const float4*)&g_Opart[((size_t)s * NROWS + row) * 32 + c4];
        O.x += o.x; O.y += o.y; O.z += o.z; O.w += o.w;
        Z += g_Zpart[s * NROWS + row];
    }
    float iz = 1.0f / Z;
    *(float4*)&out[(size_t)row * 32 + c4] =
        make_float4(O.x * iz, O.y * iz, O.z * iz, O.w * iz);
}

// ---------------- launch -------------------------------------------------------
extern "C" void kernel_launch(void* const* d_in, const int* in_sizes, int n_in,
                              void* d_out, int out_size) {
    const float* x         = (const float*)d_in[0];
    const float* vocab_emb = (const float*)d_in[1];
    const float* W_ffn     = (const float*)d_in[2];
    const float* b_ffn     = (const float*)d_in[3];
    const float* temps     = (const float*)d_in[4];
    const float* W_ref     = (const float*)d_in[5];
    const float* b_ref     = (const float*)d_in[6];
    const float* W_gate    = (const float*)d_in[7];
    const float* b_gate    = (const float*)d_in[8];
    float* out = (float*)d_out;

    build_S_tiles<<<NTILES, 256>>>(vocab_emb);
    qbuild_kernel<<<NROWS / 8, 256>>>(x, W_ffn, b_ffn, temps);
    flash_kernel<<<MTILES * NSPLIT, 128>>>();
    merge_gate_kernel<<<NROWS / 8, 256>>>(x, W_ref, b_ref, W_gate, b_gate, temps);
    flash_kernel<<<MTILES * NSPLIT, 128>>>();
    final_kernel<<<(NROWS * 8 + 255) / 256, 256>>>(out);
}